// round 5
// baseline (speedup 1.0000x reference)
#include <cuda_runtime.h>
#include <math.h>

// ---------------- problem constants ----------------
#define LN    2
#define NSEQ  196
#define DIM   768
#define PP    64
#define BB    2
#define NSUP  25
#define NQRY  50
#define NV    5
#define MS    500      // L * B*n_sup*n_views  (sup matrices)
#define MQ    1000     // L * B*n_qry*n_views  (qry matrices)
#define MTS   250      // per-L sup matrices
#define MTQ   500      // per-L qry matrices
#define GS    50       // sup groups (B*n_sup)
#define GQ    100      // qry groups (B*n_qry)
#define TRI   2080     // 64*65/2
#define SEC0  1536     // 2*768
#define SEC1  4160     // 2*2080
#define DF    7232     // 1536+4160+1536
#define NC    5

// ---------------- scratch (static device globals; allocation-free rule) ----------------
__device__ float g_gap_s[MS * DIM];
__device__ float g_gap_q[MQ * DIM];
__device__ float g_bls_s[MS * DIM];
__device__ float g_bls_q[MQ * DIM];
__device__ float g_proj_s[MS * NSEQ * PP];
__device__ float g_proj_q[MQ * NSEQ * PP];
__device__ float g_cs_s[MS * PP * PP];
__device__ float g_cs_q[MQ * PP * PP];
__device__ float g_z_s[GS * DF];
__device__ float g_z_q[GQ * DF];
__device__ float g_mu_s[BB * DF];
__device__ float g_std_s[BB * DF];
__device__ float g_mu_q[BB * DF];
__device__ float g_std_q[BB * DF];
__device__ float g_gram[BB * 75 * 25];   // rows 0..24 = K, rows 25..74 = sim

// ---------------- helpers ----------------
__device__ __forceinline__ float tukey_f(float x) {
    float s = (x > 0.0f ? 1.0f : 0.0f) - (x < 0.0f ? 1.0f : 0.0f);
    return s * sqrtf(fabsf(x) + 1e-8f);
}

__device__ __forceinline__ float block_reduce_sum(float v, float* red, int tid) {
    red[tid] = v;
    __syncthreads();
    for (int s = 128; s > 0; s >>= 1) {
        if (tid < s) red[tid] += red[tid + s];
        __syncthreads();
    }
    float r = red[0];
    __syncthreads();
    return r;
}

// ---------------- 1) gap = mean over N ----------------
__global__ void gap_kernel(const float* __restrict__ feat, int which) {
    float* out = which ? g_gap_q : g_gap_s;
    int mi = blockIdx.x;
    int d = blockIdx.y * 256 + threadIdx.x;
    const float* base = feat + (size_t)mi * NSEQ * DIM + d;
    float s = 0.0f;
    #pragma unroll 4
    for (int n = 0; n < NSEQ; n++) s += base[(size_t)n * DIM];
    out[(size_t)mi * DIM + d] = s * (1.0f / NSEQ);
}

// ---------------- 2) fused GEMM ----------------
// MODE 0: proj = feat @ cov_reducer  (ldW=64, one 64-col tile) -> g_proj
// MODE 1: bls  = mean_n tanh(feat @ w_bls + b)  (ldW=768, 12 tiles) -> g_bls
template <int MODE>
__global__ void gemm_kernel(const float* __restrict__ feat,
                            const float* __restrict__ W,
                            const float* __restrict__ bias,
                            int which) {
    __shared__ float As[32][208];      // [k][n], n padded (reads up to 207)
    __shared__ float Ws[32][64];       // [k][d_local]
    __shared__ float redg[16][64];

    int mi = blockIdx.x;
    int dtile = blockIdx.y * 64;
    int tx = threadIdx.x, ty = threadIdx.y;
    int tid = ty * 16 + tx;
    const int ldW = (MODE == 0) ? PP : DIM;
    const float* A = feat + (size_t)mi * NSEQ * DIM;

    float acc[13][4];
    #pragma unroll
    for (int r = 0; r < 13; r++)
        #pragma unroll
        for (int c = 0; c < 4; c++) acc[r][c] = 0.0f;

    for (int k0 = 0; k0 < DIM; k0 += 32) {
        __syncthreads();
        // load A chunk: 196 x 32 (float4)
        for (int idx = tid; idx < 1568; idx += 256) {
            int n = idx >> 3;
            int q = idx & 7;
            float4 v = *(const float4*)(A + (size_t)n * DIM + k0 + 4 * q);
            int kk = 4 * q;
            As[kk][n] = v.x; As[kk + 1][n] = v.y; As[kk + 2][n] = v.z; As[kk + 3][n] = v.w;
        }
        // load W chunk: 32 x 64 (float4)
        for (int idx = tid; idx < 512; idx += 256) {
            int kk = idx >> 4;
            int q = idx & 15;
            float4 v = *(const float4*)(W + (size_t)(k0 + kk) * ldW + dtile + 4 * q);
            *(float4*)&Ws[kk][4 * q] = v;
        }
        __syncthreads();
        #pragma unroll 8
        for (int kk = 0; kk < 32; kk++) {
            float w0 = Ws[kk][tx];
            float w1 = Ws[kk][tx + 16];
            float w2 = Ws[kk][tx + 32];
            float w3 = Ws[kk][tx + 48];
            #pragma unroll
            for (int r = 0; r < 13; r++) {
                float a = As[kk][ty + 16 * r];
                acc[r][0] += a * w0;
                acc[r][1] += a * w1;
                acc[r][2] += a * w2;
                acc[r][3] += a * w3;
            }
        }
    }

    if (MODE == 0) {
        float* outp = which ? g_proj_q : g_proj_s;
        #pragma unroll
        for (int r = 0; r < 13; r++) {
            int n = ty + 16 * r;
            if (n < NSEQ) {
                #pragma unroll
                for (int c = 0; c < 4; c++)
                    outp[(size_t)mi * NSEQ * PP + (size_t)n * PP + tx + 16 * c] = acc[r][c];
            }
        }
    } else {
        float* outp = which ? g_bls_q : g_bls_s;
        float bv[4];
        #pragma unroll
        for (int c = 0; c < 4; c++) bv[c] = bias[dtile + tx + 16 * c];
        float p[4] = {0.0f, 0.0f, 0.0f, 0.0f};
        #pragma unroll
        for (int r = 0; r < 13; r++) {
            int n = ty + 16 * r;
            if (n < NSEQ) {
                #pragma unroll
                for (int c = 0; c < 4; c++) p[c] += tanhf(acc[r][c] + bv[c]);
            }
        }
        __syncthreads();
        redg[ty][tx] = p[0];
        redg[ty][tx + 16] = p[1];
        redg[ty][tx + 32] = p[2];
        redg[ty][tx + 48] = p[3];
        __syncthreads();
        if (tid < 64) {
            float s = 0.0f;
            #pragma unroll
            for (int t2 = 0; t2 < 16; t2++) s += redg[t2][tid];
            outp[(size_t)mi * DIM + dtile + tid] = s * (1.0f / NSEQ);
        }
    }
}

// ---------------- 3) cov + Newton-Schulz matrix sqrt (per matrix) ----------------
// dyn smem: X[196*65] + Y/Z/T[64*65 each] + red[256] + mean[64]
#define CS_SMEM_FLOATS (NSEQ * 65 + 3 * 64 * 65 + 256 + 64)

__global__ void covsqrt_kernel(int which) {
    extern __shared__ float sh[];
    float* X = sh;
    float* Yb = X + NSEQ * 65;
    float* Zb = Yb + 64 * 65;
    float* Tb = Zb + 64 * 65;
    float* red = Tb + 64 * 65;
    float* mean = red + 256;

    const float* proj = which ? g_proj_q : g_proj_s;
    float* cs = which ? g_cs_q : g_cs_s;
    int mi = blockIdx.x;
    int tx = threadIdx.x, ty = threadIdx.y;
    int tid = ty * 16 + tx;

    // load x (padded ld=65)
    for (int idx = tid; idx < NSEQ * PP; idx += 256) {
        int n = idx >> 6;
        int p = idx & 63;
        X[n * 65 + p] = proj[(size_t)mi * NSEQ * PP + idx];
    }
    __syncthreads();
    // column means
    if (tid < 64) {
        float s = 0.0f;
        for (int n = 0; n < NSEQ; n++) s += X[n * 65 + tid];
        mean[tid] = s * (1.0f / NSEQ);
    }
    __syncthreads();
    // center
    for (int idx = tid; idx < NSEQ * PP; idx += 256) {
        int n = idx >> 6;
        int p = idx & 63;
        X[n * 65 + p] -= mean[p];
    }
    __syncthreads();

    // cov = X^T X / 195 + 1e-5 I (4x4 register tile per thread)
    float cacc[4][4];
    #pragma unroll
    for (int i = 0; i < 4; i++)
        #pragma unroll
        for (int j = 0; j < 4; j++) cacc[i][j] = 0.0f;
    for (int n = 0; n < NSEQ; n++) {
        float a[4], b[4];
        #pragma unroll
        for (int i = 0; i < 4; i++) a[i] = X[n * 65 + ty + 16 * i];
        #pragma unroll
        for (int j = 0; j < 4; j++) b[j] = X[n * 65 + tx + 16 * j];
        #pragma unroll
        for (int i = 0; i < 4; i++)
            #pragma unroll
            for (int j = 0; j < 4; j++) cacc[i][j] += a[i] * b[j];
    }
    float ss = 0.0f;
    #pragma unroll
    for (int i = 0; i < 4; i++) {
        int p = ty + 16 * i;
        #pragma unroll
        for (int j = 0; j < 4; j++) {
            int q = tx + 16 * j;
            float v = cacc[i][j] * (1.0f / 195.0f) + ((p == q) ? 1e-5f : 0.0f);
            Yb[p * 65 + q] = v;
            ss += v * v;
        }
    }
    float total = block_reduce_sum(ss, red, tid);
    float norm = sqrtf(total);
    float inv = 1.0f / (norm + 1e-8f);
    // Y = cov/(norm+eps), Z = I
    #pragma unroll
    for (int i = 0; i < 4; i++) {
        int p = ty + 16 * i;
        #pragma unroll
        for (int j = 0; j < 4; j++) {
            int q = tx + 16 * j;
            Yb[p * 65 + q] *= inv;
            Zb[p * 65 + q] = (p == q) ? 1.0f : 0.0f;
        }
    }
    __syncthreads();

    for (int it = 0; it < 3; it++) {
        // T = 1.5 I - 0.5 * (Z @ Y)
        float tacc[4][4];
        #pragma unroll
        for (int i = 0; i < 4; i++)
            #pragma unroll
            for (int j = 0; j < 4; j++) tacc[i][j] = 0.0f;
        for (int k = 0; k < 64; k++) {
            float a[4], b[4];
            #pragma unroll
            for (int i = 0; i < 4; i++) a[i] = Zb[(ty + 16 * i) * 65 + k];
            #pragma unroll
            for (int j = 0; j < 4; j++) b[j] = Yb[k * 65 + tx + 16 * j];
            #pragma unroll
            for (int i = 0; i < 4; i++)
                #pragma unroll
                for (int j = 0; j < 4; j++) tacc[i][j] += a[i] * b[j];
        }
        #pragma unroll
        for (int i = 0; i < 4; i++) {
            int p = ty + 16 * i;
            #pragma unroll
            for (int j = 0; j < 4; j++) {
                int q = tx + 16 * j;
                Tb[p * 65 + q] = ((p == q) ? 1.5f : 0.0f) - 0.5f * tacc[i][j];
            }
        }
        __syncthreads();
        // Ynew = Y@T ; Znew = T@Z  (into registers, then write back)
        float yacc[4][4], zacc[4][4];
        #pragma unroll
        for (int i = 0; i < 4; i++)
            #pragma unroll
            for (int j = 0; j < 4; j++) { yacc[i][j] = 0.0f; zacc[i][j] = 0.0f; }
        for (int k = 0; k < 64; k++) {
            float ya[4], tb[4], ta[4], zb2[4];
            #pragma unroll
            for (int i = 0; i < 4; i++) {
                ya[i] = Yb[(ty + 16 * i) * 65 + k];
                ta[i] = Tb[(ty + 16 * i) * 65 + k];
            }
            #pragma unroll
            for (int j = 0; j < 4; j++) {
                tb[j] = Tb[k * 65 + tx + 16 * j];
                zb2[j] = Zb[k * 65 + tx + 16 * j];
            }
            #pragma unroll
            for (int i = 0; i < 4; i++)
                #pragma unroll
                for (int j = 0; j < 4; j++) {
                    yacc[i][j] += ya[i] * tb[j];
                    zacc[i][j] += ta[i] * zb2[j];
                }
        }
        __syncthreads();
        #pragma unroll
        for (int i = 0; i < 4; i++) {
            int p = ty + 16 * i;
            #pragma unroll
            for (int j = 0; j < 4; j++) {
                int q = tx + 16 * j;
                Yb[p * 65 + q] = yacc[i][j];
                Zb[p * 65 + q] = zacc[i][j];
            }
        }
        __syncthreads();
    }

    float sc = sqrtf(norm + 1e-8f);
    #pragma unroll
    for (int i = 0; i < 4; i++) {
        int p = ty + 16 * i;
        #pragma unroll
        for (int j = 0; j < 4; j++) {
            int q = tx + 16 * j;
            cs[(size_t)mi * 4096 + p * 64 + q] = Yb[p * 65 + q] * sc;
        }
    }
}

// ---------------- 4) fuse: view-mean + tukey + sectioned l2norm ----------------
__global__ void fuse_kernel(int which) {
    const float* gap = which ? g_gap_q : g_gap_s;
    const float* cs = which ? g_cs_q : g_cs_s;
    const float* bls = which ? g_bls_q : g_bls_s;
    float* z = which ? g_z_q : g_z_s;
    int Mt = which ? MTQ : MTS;

    __shared__ float buf[DF];
    __shared__ float red[256];
    int g = blockIdx.x;
    int tid = threadIdx.x;
    int m0 = g * NV;

    float ss0 = 0.0f, ss1 = 0.0f, ss2 = 0.0f;

    // gap section [0,1536)
    for (int j = tid; j < SEC0; j += 256) {
        int l = j / DIM;
        int f = j - l * DIM;
        const float* src = gap + ((size_t)(l * Mt + m0)) * DIM + f;
        float v = 0.0f;
        #pragma unroll
        for (int vi = 0; vi < NV; vi++) v += src[(size_t)vi * DIM];
        v *= (1.0f / NV);
        float t = tukey_f(v);
        buf[j] = t;
        ss0 += t * t;
    }
    // cov section [1536,5696)
    for (int j = tid; j < SEC1; j += 256) {
        int l = j / TRI;
        int f = j - l * TRI;
        int i = 0, rem = f;
        while (rem >= 64 - i) { rem -= 64 - i; i++; }
        int jj = i + rem;
        const float* src = cs + ((size_t)(l * Mt + m0)) * 4096 + i * 64 + jj;
        float v = 0.0f;
        #pragma unroll
        for (int vi = 0; vi < NV; vi++) v += src[(size_t)vi * 4096];
        v *= (1.0f / NV);
        float t = tukey_f(v);
        buf[SEC0 + j] = t;
        ss1 += t * t;
    }
    // bls section [5696,7232)
    for (int j = tid; j < SEC0; j += 256) {
        int l = j / DIM;
        int f = j - l * DIM;
        const float* src = bls + ((size_t)(l * Mt + m0)) * DIM + f;
        float v = 0.0f;
        #pragma unroll
        for (int vi = 0; vi < NV; vi++) v += src[(size_t)vi * DIM];
        v *= (1.0f / NV);
        float t = tukey_f(v);
        buf[SEC0 + SEC1 + j] = t;
        ss2 += t * t;
    }
    __syncthreads();
    float S0 = block_reduce_sum(ss0, red, tid);
    float S1 = block_reduce_sum(ss1, red, tid);
    float S2 = block_reduce_sum(ss2, red, tid);
    float inv0 = 1.0f / fmaxf(sqrtf(S0), 1e-12f) * 1.0f;
    float inv1 = 1.0f / fmaxf(sqrtf(S1), 1e-12f) * 0.8f;
    float inv2 = 1.0f / fmaxf(sqrtf(S2), 1e-12f) * 0.1f;

    for (int j = tid; j < DF; j += 256) {
        float w = (j < SEC0) ? inv0 : (j < SEC0 + SEC1) ? inv1 : inv2;
        z[(size_t)g * DF + j] = buf[j] * w;
    }
}

// ---------------- 5) per-(b,feature) stats ----------------
__global__ void stats_kernel() {
    int idx = blockIdx.x * 256 + threadIdx.x;
    if (idx >= BB * DF) return;
    int b = idx / DF;
    int f = idx - b * DF;
    {
        const float* zs = g_z_s + (size_t)b * NSUP * DF + f;
        float m = 0.0f;
        for (int s = 0; s < NSUP; s++) m += zs[(size_t)s * DF];
        m *= (1.0f / NSUP);
        float v = 0.0f;
        for (int s = 0; s < NSUP; s++) { float d = zs[(size_t)s * DF] - m; v += d * d; }
        v *= (1.0f / (NSUP - 1));
        g_mu_s[idx] = m;
        g_std_s[idx] = sqrtf(v) + 1e-8f;
    }
    {
        const float* zq = g_z_q + (size_t)b * NQRY * DF + f;
        float m = 0.0f;
        for (int s = 0; s < NQRY; s++) m += zq[(size_t)s * DF];
        m *= (1.0f / NQRY);
        float v = 0.0f;
        for (int s = 0; s < NQRY; s++) { float d = zq[(size_t)s * DF] - m; v += d * d; }
        v *= (1.0f / (NQRY - 1));
        g_mu_q[idx] = m;
        g_std_q[idx] = sqrtf(v) + 1e-8f;
    }
}

// ---------------- 6) center/standardize + row l2norm ----------------
// which=0: z_sup <- l2norm(z_sup - mu_s)
// which=1: z_qry <- l2norm((z_qry - mu_q)/std_q * std_s)   [mu_s cancels]
__global__ void rownorm_kernel(int which) {
    __shared__ float red[256];
    int g = blockIdx.x;
    int tid = threadIdx.x;
    if (which == 0) {
        int b = g / NSUP;
        float* z = g_z_s + (size_t)g * DF;
        const float* mu = g_mu_s + (size_t)b * DF;
        float ss = 0.0f;
        for (int f = tid; f < DF; f += 256) { float v = z[f] - mu[f]; ss += v * v; }
        float S = block_reduce_sum(ss, red, tid);
        float inv = 1.0f / fmaxf(sqrtf(S), 1e-12f);
        for (int f = tid; f < DF; f += 256) z[f] = (z[f] - mu[f]) * inv;
    } else {
        int b = g / NQRY;
        float* z = g_z_q + (size_t)g * DF;
        const float* muq = g_mu_q + (size_t)b * DF;
        const float* sdq = g_std_q + (size_t)b * DF;
        const float* sds = g_std_s + (size_t)b * DF;
        float ss = 0.0f;
        for (int f = tid; f < DF; f += 256) {
            float v = (z[f] - muq[f]) / sdq[f] * sds[f];
            ss += v * v;
        }
        float S = block_reduce_sum(ss, red, tid);
        float inv = 1.0f / fmaxf(sqrtf(S), 1e-12f);
        for (int f = tid; f < DF; f += 256) {
            float v = (z[f] - muq[f]) / sdq[f] * sds[f];
            z[f] = v * inv;
        }
    }
}

// ---------------- 7) gram: K (25x25) and sim (50x25) per b ----------------
__global__ void gram_kernel() {
    int b = blockIdx.x;
    int i = blockIdx.y;   // 0..74
    int tid = threadIdx.x;
    const float* rowi = (i < NSUP)
        ? g_z_s + (size_t)(b * NSUP + i) * DF
        : g_z_q + (size_t)(b * NQRY + (i - NSUP)) * DF;
    const float* zsb = g_z_s + (size_t)b * NSUP * DF;

    float part[NSUP];
    #pragma unroll
    for (int j = 0; j < NSUP; j++) part[j] = 0.0f;
    for (int f = tid; f < DF; f += 256) {
        float a = rowi[f];
        #pragma unroll
        for (int j = 0; j < NSUP; j++) part[j] += a * zsb[(size_t)j * DF + f];
    }
    __shared__ float red[256];
    for (int j = 0; j < NSUP; j++) {
        red[tid] = part[j];
        __syncthreads();
        for (int s = 128; s > 0; s >>= 1) {
            if (tid < s) red[tid] += red[tid + s];
            __syncthreads();
        }
        if (tid == 0) g_gram[(b * 75 + i) * 25 + j] = red[0];
        __syncthreads();
    }
}

// ---------------- 8) ridge solve + output ----------------
__global__ void solve_kernel(const int* __restrict__ y_sup, float* __restrict__ out) {
    int b = blockIdx.x;
    int tid = threadIdx.x;   // 32 threads
    __shared__ float Ab[25][31];     // augmented [K+lam*I | Y] (30 cols used)
    __shared__ float alpha[25][5];
    const float lam = 0.1f * ((float)DF / 500.0f);

    for (int idx = tid; idx < 25 * 30; idx += 32) {
        int i = idx / 30;
        int j = idx - i * 30;
        if (j < 25) {
            Ab[i][j] = g_gram[(b * 75 + i) * 25 + j] + ((i == j) ? lam : 0.0f);
        } else {
            int c = j - 25;
            Ab[i][j] = (y_sup[b * NSUP + i] == c) ? 1.0f : 0.0f;
        }
    }
    __syncthreads();
    // Gauss-Jordan (SPD + lam*I: no pivoting needed)
    for (int k = 0; k < 25; k++) {
        if (tid < 25 && tid != k) {
            float factor = Ab[tid][k] / Ab[k][k];
            for (int j = k; j < 30; j++) Ab[tid][j] -= factor * Ab[k][j];
        }
        __syncthreads();
    }
    for (int idx = tid; idx < 125; idx += 32) {
        int i = idx / 5;
        int c = idx - i * 5;
        alpha[i][c] = Ab[i][25 + c] / Ab[i][i];
    }
    __syncthreads();
    for (int idx = tid; idx < NQRY * NC; idx += 32) {
        int q = idx / NC;
        int c = idx - q * NC;
        float s = 0.0f;
        #pragma unroll
        for (int j = 0; j < 25; j++) s += g_gram[(b * 75 + 25 + q) * 25 + j] * alpha[j][c];
        out[((size_t)b * NQRY + q) * NC + c] = 20.0f * s;
    }
}

// ---------------- launch ----------------
extern "C" void kernel_launch(void* const* d_in, const int* in_sizes, int n_in,
                              void* d_out, int out_size) {
    const float* feats_sup   = (const float*)d_in[0];
    const float* feats_qry   = (const float*)d_in[1];
    const float* cov_reducer = (const float*)d_in[2];
    const float* w_bls       = (const float*)d_in[3];
    const float* b_bls       = (const float*)d_in[4];
    const int*   y_sup       = (const int*)d_in[5];
    float* out = (float*)d_out;

    static const size_t CS_SMEM = (size_t)CS_SMEM_FLOATS * sizeof(float);
    cudaFuncSetAttribute(covsqrt_kernel, cudaFuncAttributeMaxDynamicSharedMemorySize, (int)CS_SMEM);

    dim3 blk2d(16, 16);

    // gap
    gap_kernel<<<dim3(MS, 3), 256>>>(feats_sup, 0);
    gap_kernel<<<dim3(MQ, 3), 256>>>(feats_qry, 1);

    // projection GEMM (feat @ cov_reducer)
    gemm_kernel<0><<<dim3(MS, 1), blk2d>>>(feats_sup, cov_reducer, nullptr, 0);
    gemm_kernel<0><<<dim3(MQ, 1), blk2d>>>(feats_qry, cov_reducer, nullptr, 1);

    // BLS GEMM (tanh(feat@W+b).mean)
    gemm_kernel<1><<<dim3(MS, 12), blk2d>>>(feats_sup, w_bls, b_bls, 0);
    gemm_kernel<1><<<dim3(MQ, 12), blk2d>>>(feats_qry, w_bls, b_bls, 1);

    // cov + Newton-Schulz sqrt
    covsqrt_kernel<<<MS, blk2d, CS_SMEM>>>(0);
    covsqrt_kernel<<<MQ, blk2d, CS_SMEM>>>(1);

    // fuse
    fuse_kernel<<<GS, 256>>>(0);
    fuse_kernel<<<GQ, 256>>>(1);

    // stats
    stats_kernel<<<(BB * DF + 255) / 256, 256>>>();

    // center + l2norm rows
    rownorm_kernel<<<GS, 256>>>(0);
    rownorm_kernel<<<GQ, 256>>>(1);

    // gram (K and sim)
    gram_kernel<<<dim3(BB, 75), 256>>>();

    // ridge solve + logits
    solve_kernel<<<BB, 32>>>(y_sup, out);
}

// round 9
// speedup vs baseline: 1.0376x; 1.0376x over previous
#include <cuda_runtime.h>
#include <math.h>
#include <stdint.h>

// ---------------- problem constants ----------------
#define LN    2
#define NSEQ  196
#define DIM   768
#define PP    64
#define BB    2
#define NSUP  25
#define NQRY  50
#define NV    5
#define MS    500      // L * B*n_sup*n_views  (sup matrices)
#define MQ    1000     // L * B*n_qry*n_views  (qry matrices)
#define MTS   250      // per-L sup matrices
#define MTQ   500      // per-L qry matrices
#define GS    50       // sup groups (B*n_sup)
#define GQ    100      // qry groups (B*n_qry)
#define TRI   2080     // 64*65/2
#define SEC0  1536     // 2*768
#define SEC1  4160     // 2*2080
#define DF    7232     // 1536+4160+1536
#define NC    5

// ---------------- scratch (static device globals; allocation-free rule) ----------------
__device__ float g_gap_s[MS * DIM];
__device__ float g_gap_q[MQ * DIM];
__device__ float g_bls_s[MS * DIM];
__device__ float g_bls_q[MQ * DIM];
__device__ float g_proj_s[MS * NSEQ * PP];
__device__ float g_proj_q[MQ * NSEQ * PP];
__device__ float g_cs_s[MS * PP * PP];
__device__ float g_cs_q[MQ * PP * PP];
__device__ float g_z_s[GS * DF];
__device__ float g_z_q[GQ * DF];
__device__ float g_mu_s[BB * DF];
__device__ float g_std_s[BB * DF];
__device__ float g_mu_q[BB * DF];
__device__ float g_std_q[BB * DF];
__device__ float g_gram[BB * 75 * 25];   // rows 0..24 = K, rows 25..74 = sim

// ---------------- helpers ----------------
__device__ __forceinline__ float tukey_f(float x) {
    float s = (x > 0.0f ? 1.0f : 0.0f) - (x < 0.0f ? 1.0f : 0.0f);
    return s * sqrtf(fabsf(x) + 1e-8f);
}

__device__ __forceinline__ float block_reduce_sum(float v, float* red, int tid) {
    red[tid] = v;
    __syncthreads();
    for (int s = 128; s > 0; s >>= 1) {
        if (tid < s) red[tid] += red[tid + s];
        __syncthreads();
    }
    float r = red[0];
    __syncthreads();
    return r;
}

__device__ __forceinline__ uint32_t f2tf32(float x) {
    uint32_t u;
    asm("cvt.rna.tf32.f32 %0, %1;" : "=r"(u) : "f"(x));
    return u;
}

__device__ __forceinline__ void mma_tf32(float c[4], uint32_t a0, uint32_t a1,
                                         uint32_t a2, uint32_t a3,
                                         uint32_t b0, uint32_t b1) {
    asm volatile(
        "mma.sync.aligned.m16n8k8.row.col.f32.tf32.tf32.f32 "
        "{%0,%1,%2,%3}, {%4,%5,%6,%7}, {%8,%9}, {%0,%1,%2,%3};"
        : "+f"(c[0]), "+f"(c[1]), "+f"(c[2]), "+f"(c[3])
        : "r"(a0), "r"(a1), "r"(a2), "r"(a3), "r"(b0), "r"(b1));
}

// ---------------- 1) gap = mean over N ----------------
__global__ void gap_kernel(const float* __restrict__ feat, int which) {
    float* out = which ? g_gap_q : g_gap_s;
    int mi = blockIdx.x;
    int d = blockIdx.y * 256 + threadIdx.x;
    const float* base = feat + (size_t)mi * NSEQ * DIM + d;
    float s = 0.0f;
    #pragma unroll 4
    for (int n = 0; n < NSEQ; n++) s += base[(size_t)n * DIM];
    out[(size_t)mi * DIM + d] = s * (1.0f / NSEQ);
}

// ---------------- 2a) projection GEMM (fp32, MODE 0 of old kernel) ----------------
__global__ void proj_gemm_kernel(const float* __restrict__ feat,
                                 const float* __restrict__ W,
                                 int which) {
    __shared__ float As[32][208];
    __shared__ float Ws[32][64];

    int mi = blockIdx.x;
    int tx = threadIdx.x, ty = threadIdx.y;
    int tid = ty * 16 + tx;
    const float* A = feat + (size_t)mi * NSEQ * DIM;

    float acc[13][4];
    #pragma unroll
    for (int r = 0; r < 13; r++)
        #pragma unroll
        for (int c = 0; c < 4; c++) acc[r][c] = 0.0f;

    for (int k0 = 0; k0 < DIM; k0 += 32) {
        __syncthreads();
        for (int idx = tid; idx < 1568; idx += 256) {
            int n = idx >> 3;
            int q = idx & 7;
            float4 v = *(const float4*)(A + (size_t)n * DIM + k0 + 4 * q);
            int kk = 4 * q;
            As[kk][n] = v.x; As[kk + 1][n] = v.y; As[kk + 2][n] = v.z; As[kk + 3][n] = v.w;
        }
        for (int idx = tid; idx < 512; idx += 256) {
            int kk = idx >> 4;
            int q = idx & 15;
            float4 v = *(const float4*)(W + (size_t)(k0 + kk) * PP + 4 * q);
            *(float4*)&Ws[kk][4 * q] = v;
        }
        __syncthreads();
        #pragma unroll 8
        for (int kk = 0; kk < 32; kk++) {
            float w0 = Ws[kk][tx];
            float w1 = Ws[kk][tx + 16];
            float w2 = Ws[kk][tx + 32];
            float w3 = Ws[kk][tx + 48];
            #pragma unroll
            for (int r = 0; r < 13; r++) {
                float a = As[kk][ty + 16 * r];
                acc[r][0] += a * w0;
                acc[r][1] += a * w1;
                acc[r][2] += a * w2;
                acc[r][3] += a * w3;
            }
        }
    }

    float* outp = which ? g_proj_q : g_proj_s;
    #pragma unroll
    for (int r = 0; r < 13; r++) {
        int n = ty + 16 * r;
        if (n < NSEQ) {
            #pragma unroll
            for (int c = 0; c < 4; c++)
                outp[(size_t)mi * NSEQ * PP + (size_t)n * PP + tx + 16 * c] = acc[r][c];
        }
    }
}

// ---------------- 2b) BLS GEMM via tf32 tensor cores ----------------
// bls = mean_n tanh(feat @ w_bls + b)
// CTA = (matrix, n-tile of 64). 8 warps: wm in 0..3 (M split), wn in 0..1 (N split).
// Warp handles m-tiles {wm, wm+4, wm+8, wm+12(<13)}, cols [wn*32, wn*32+32).
#define A_LD 217   // conflict-free transpose stores: bank = 4q + m, all distinct
#define W_LD 72    // frag loads: bank = 8*tig + gid, all 32 distinct

__global__ void __launch_bounds__(256, 2)
bls_mma_kernel(const float* __restrict__ feat,
               const float* __restrict__ W,
               const float* __restrict__ bias,
               int which) {
    __shared__ uint32_t As[32][A_LD];   // tf32 bits, [k][m], m<208 (rows>=196 zero)
    __shared__ uint32_t Ws[32][W_LD];   // tf32 bits, [k][n]
    __shared__ float colsum[4][64];

    int mi = blockIdx.x;
    int nt = blockIdx.y;               // 0..11
    int n0 = nt * 64;
    const float* A = feat + (size_t)mi * NSEQ * DIM;

    int tid = threadIdx.x;
    int lane = tid & 31;
    int warp = tid >> 5;
    int wm = warp & 3;                 // M split
    int wn = warp >> 2;                // N split
    int gid = lane >> 2;               // 0..7
    int tig = lane & 3;                // 0..3

    float acc[4][4][4];                // [mt][nf][4]
    #pragma unroll
    for (int mt = 0; mt < 4; mt++)
        #pragma unroll
        for (int nf = 0; nf < 4; nf++)
            #pragma unroll
            for (int c = 0; c < 4; c++) acc[mt][nf][c] = 0.0f;

    for (int k0 = 0; k0 < DIM; k0 += 32) {
        __syncthreads();
        // load A chunk 208x32 (transpose to [k][m]), zero-pad rows >= 196
        for (int idx = tid; idx < 1664; idx += 256) {
            int m = idx >> 3;
            int q = idx & 7;
            float4 v = make_float4(0.f, 0.f, 0.f, 0.f);
            if (m < NSEQ) v = *(const float4*)(A + (size_t)m * DIM + k0 + 4 * q);
            int kk = 4 * q;
            As[kk][m]     = f2tf32(v.x);
            As[kk + 1][m] = f2tf32(v.y);
            As[kk + 2][m] = f2tf32(v.z);
            As[kk + 3][m] = f2tf32(v.w);
        }
        // load W chunk 32x64
        for (int idx = tid; idx < 512; idx += 256) {
            int kk = idx >> 4;
            int q = idx & 15;
            float4 v = *(const float4*)(W + (size_t)(k0 + kk) * DIM + n0 + 4 * q);
            uint4 u;
            u.x = f2tf32(v.x); u.y = f2tf32(v.y); u.z = f2tf32(v.z); u.w = f2tf32(v.w);
            *(uint4*)&Ws[kk][4 * q] = u;
        }
        __syncthreads();

        #pragma unroll
        for (int kt = 0; kt < 4; kt++) {
            int kb = kt * 8;
            // B fragments (4 n8-tiles within this warp's 32 cols)
            uint32_t b0[4], b1[4];
            #pragma unroll
            for (int nf = 0; nf < 4; nf++) {
                int nc = wn * 32 + nf * 8 + gid;
                b0[nf] = Ws[kb + tig][nc];
                b1[nf] = Ws[kb + tig + 4][nc];
            }
            // A fragments per m-tile, then mma
            #pragma unroll
            for (int mt = 0; mt < 4; mt++) {
                int mtg = wm + 4 * mt;
                if (mtg < 13) {
                    int mr = mtg * 16;
                    uint32_t a0 = As[kb + tig][mr + gid];
                    uint32_t a1 = As[kb + tig][mr + gid + 8];
                    uint32_t a2 = As[kb + tig + 4][mr + gid];
                    uint32_t a3 = As[kb + tig + 4][mr + gid + 8];
                    #pragma unroll
                    for (int nf = 0; nf < 4; nf++)
                        mma_tf32(acc[mt][nf], a0, a1, a2, a3, b0[nf], b1[nf]);
                }
            }
        }
    }

    // epilogue: tanh(acc + bias) column-mean over valid rows
    #pragma unroll
    for (int nf = 0; nf < 4; nf++) {
        int cb = n0 + wn * 32 + nf * 8 + 2 * tig;
        float bv0 = bias[cb];
        float bv1 = bias[cb + 1];
        float p0 = 0.0f, p1 = 0.0f;
        #pragma unroll
        for (int mt = 0; mt < 4; mt++) {
            int mtg = wm + 4 * mt;
            if (mtg < 13) {
                int r0 = mtg * 16 + gid;
                int r1 = r0 + 8;
                if (r0 < NSEQ) {
                    p0 += tanhf(acc[mt][nf][0] + bv0);
                    p1 += tanhf(acc[mt][nf][1] + bv1);
                }
                if (r1 < NSEQ) {
                    p0 += tanhf(acc[mt][nf][2] + bv0);
                    p1 += tanhf(acc[mt][nf][3] + bv1);
                }
            }
        }
        // reduce over gid (lane bits 2..4)
        #pragma unroll
        for (int off = 4; off <= 16; off <<= 1) {
            p0 += __shfl_xor_sync(0xffffffff, p0, off);
            p1 += __shfl_xor_sync(0xffffffff, p1, off);
        }
        if (gid == 0) {
            colsum[wm][wn * 32 + nf * 8 + 2 * tig]     = p0;
            colsum[wm][wn * 32 + nf * 8 + 2 * tig + 1] = p1;
        }
    }
    __syncthreads();
    if (tid < 64) {
        float s = colsum[0][tid] + colsum[1][tid] + colsum[2][tid] + colsum[3][tid];
        float* outp = which ? g_bls_q : g_bls_s;
        outp[(size_t)mi * DIM + n0 + tid] = s * (1.0f / NSEQ);
    }
}

// ---------------- 3) cov + Newton-Schulz matrix sqrt (per matrix) ----------------
#define CS_SMEM_FLOATS (NSEQ * 65 + 3 * 64 * 65 + 256 + 64)

__global__ void covsqrt_kernel(int which) {
    extern __shared__ float sh[];
    float* X = sh;
    float* Yb = X + NSEQ * 65;
    float* Zb = Yb + 64 * 65;
    float* Tb = Zb + 64 * 65;
    float* red = Tb + 64 * 65;
    float* mean = red + 256;

    const float* proj = which ? g_proj_q : g_proj_s;
    float* cs = which ? g_cs_q : g_cs_s;
    int mi = blockIdx.x;
    int tx = threadIdx.x, ty = threadIdx.y;
    int tid = ty * 16 + tx;

    for (int idx = tid; idx < NSEQ * PP; idx += 256) {
        int n = idx >> 6;
        int p = idx & 63;
        X[n * 65 + p] = proj[(size_t)mi * NSEQ * PP + idx];
    }
    __syncthreads();
    if (tid < 64) {
        float s = 0.0f;
        for (int n = 0; n < NSEQ; n++) s += X[n * 65 + tid];
        mean[tid] = s * (1.0f / NSEQ);
    }
    __syncthreads();
    for (int idx = tid; idx < NSEQ * PP; idx += 256) {
        int n = idx >> 6;
        int p = idx & 63;
        X[n * 65 + p] -= mean[p];
    }
    __syncthreads();

    float cacc[4][4];
    #pragma unroll
    for (int i = 0; i < 4; i++)
        #pragma unroll
        for (int j = 0; j < 4; j++) cacc[i][j] = 0.0f;
    for (int n = 0; n < NSEQ; n++) {
        float a[4], b[4];
        #pragma unroll
        for (int i = 0; i < 4; i++) a[i] = X[n * 65 + ty + 16 * i];
        #pragma unroll
        for (int j = 0; j < 4; j++) b[j] = X[n * 65 + tx + 16 * j];
        #pragma unroll
        for (int i = 0; i < 4; i++)
            #pragma unroll
            for (int j = 0; j < 4; j++) cacc[i][j] += a[i] * b[j];
    }
    float ss = 0.0f;
    #pragma unroll
    for (int i = 0; i < 4; i++) {
        int p = ty + 16 * i;
        #pragma unroll
        for (int j = 0; j < 4; j++) {
            int q = tx + 16 * j;
            float v = cacc[i][j] * (1.0f / 195.0f) + ((p == q) ? 1e-5f : 0.0f);
            Yb[p * 65 + q] = v;
            ss += v * v;
        }
    }
    float total = block_reduce_sum(ss, red, tid);
    float norm = sqrtf(total);
    float inv = 1.0f / (norm + 1e-8f);
    #pragma unroll
    for (int i = 0; i < 4; i++) {
        int p = ty + 16 * i;
        #pragma unroll
        for (int j = 0; j < 4; j++) {
            int q = tx + 16 * j;
            Yb[p * 65 + q] *= inv;
            Zb[p * 65 + q] = (p == q) ? 1.0f : 0.0f;
        }
    }
    __syncthreads();

    for (int it = 0; it < 3; it++) {
        float tacc[4][4];
        #pragma unroll
        for (int i = 0; i < 4; i++)
            #pragma unroll
            for (int j = 0; j < 4; j++) tacc[i][j] = 0.0f;
        for (int k = 0; k < 64; k++) {
            float a[4], b[4];
            #pragma unroll
            for (int i = 0; i < 4; i++) a[i] = Zb[(ty + 16 * i) * 65 + k];
            #pragma unroll
            for (int j = 0; j < 4; j++) b[j] = Yb[k * 65 + tx + 16 * j];
            #pragma unroll
            for (int i = 0; i < 4; i++)
                #pragma unroll
                for (int j = 0; j < 4; j++) tacc[i][j] += a[i] * b[j];
        }
        #pragma unroll
        for (int i = 0; i < 4; i++) {
            int p = ty + 16 * i;
            #pragma unroll
            for (int j = 0; j < 4; j++) {
                int q = tx + 16 * j;
                Tb[p * 65 + q] = ((p == q) ? 1.5f : 0.0f) - 0.5f * tacc[i][j];
            }
        }
        __syncthreads();
        float yacc[4][4], zacc[4][4];
        #pragma unroll
        for (int i = 0; i < 4; i++)
            #pragma unroll
            for (int j = 0; j < 4; j++) { yacc[i][j] = 0.0f; zacc[i][j] = 0.0f; }
        for (int k = 0; k < 64; k++) {
            float ya[4], tb[4], ta[4], zb2[4];
            #pragma unroll
            for (int i = 0; i < 4; i++) {
                ya[i] = Yb[(ty + 16 * i) * 65 + k];
                ta[i] = Tb[(ty + 16 * i) * 65 + k];
            }
            #pragma unroll
            for (int j = 0; j < 4; j++) {
                tb[j] = Tb[k * 65 + tx + 16 * j];
                zb2[j] = Zb[k * 65 + tx + 16 * j];
            }
            #pragma unroll
            for (int i = 0; i < 4; i++)
                #pragma unroll
                for (int j = 0; j < 4; j++) {
                    yacc[i][j] += ya[i] * tb[j];
                    zacc[i][j] += ta[i] * zb2[j];
                }
        }
        __syncthreads();
        #pragma unroll
        for (int i = 0; i < 4; i++) {
            int p = ty + 16 * i;
            #pragma unroll
            for (int j = 0; j < 4; j++) {
                int q = tx + 16 * j;
                Yb[p * 65 + q] = yacc[i][j];
                Zb[p * 65 + q] = zacc[i][j];
            }
        }
        __syncthreads();
    }

    float sc = sqrtf(norm + 1e-8f);
    #pragma unroll
    for (int i = 0; i < 4; i++) {
        int p = ty + 16 * i;
        #pragma unroll
        for (int j = 0; j < 4; j++) {
            int q = tx + 16 * j;
            cs[(size_t)mi * 4096 + p * 64 + q] = Yb[p * 65 + q] * sc;
        }
    }
}

// ---------------- 4) fuse ----------------
__global__ void fuse_kernel(int which) {
    const float* gap = which ? g_gap_q : g_gap_s;
    const float* cs = which ? g_cs_q : g_cs_s;
    const float* bls = which ? g_bls_q : g_bls_s;
    float* z = which ? g_z_q : g_z_s;
    int Mt = which ? MTQ : MTS;

    __shared__ float buf[DF];
    __shared__ float red[256];
    int g = blockIdx.x;
    int tid = threadIdx.x;
    int m0 = g * NV;

    float ss0 = 0.0f, ss1 = 0.0f, ss2 = 0.0f;

    for (int j = tid; j < SEC0; j += 256) {
        int l = j / DIM;
        int f = j - l * DIM;
        const float* src = gap + ((size_t)(l * Mt + m0)) * DIM + f;
        float v = 0.0f;
        #pragma unroll
        for (int vi = 0; vi < NV; vi++) v += src[(size_t)vi * DIM];
        v *= (1.0f / NV);
        float t = tukey_f(v);
        buf[j] = t;
        ss0 += t * t;
    }
    for (int j = tid; j < SEC1; j += 256) {
        int l = j / TRI;
        int f = j - l * TRI;
        int i = 0, rem = f;
        while (rem >= 64 - i) { rem -= 64 - i; i++; }
        int jj = i + rem;
        const float* src = cs + ((size_t)(l * Mt + m0)) * 4096 + i * 64 + jj;
        float v = 0.0f;
        #pragma unroll
        for (int vi = 0; vi < NV; vi++) v += src[(size_t)vi * 4096];
        v *= (1.0f / NV);
        float t = tukey_f(v);
        buf[SEC0 + j] = t;
        ss1 += t * t;
    }
    for (int j = tid; j < SEC0; j += 256) {
        int l = j / DIM;
        int f = j - l * DIM;
        const float* src = bls + ((size_t)(l * Mt + m0)) * DIM + f;
        float v = 0.0f;
        #pragma unroll
        for (int vi = 0; vi < NV; vi++) v += src[(size_t)vi * DIM];
        v *= (1.0f / NV);
        float t = tukey_f(v);
        buf[SEC0 + SEC1 + j] = t;
        ss2 += t * t;
    }
    __syncthreads();
    float S0 = block_reduce_sum(ss0, red, tid);
    float S1 = block_reduce_sum(ss1, red, tid);
    float S2 = block_reduce_sum(ss2, red, tid);
    float inv0 = 1.0f / fmaxf(sqrtf(S0), 1e-12f) * 1.0f;
    float inv1 = 1.0f / fmaxf(sqrtf(S1), 1e-12f) * 0.8f;
    float inv2 = 1.0f / fmaxf(sqrtf(S2), 1e-12f) * 0.1f;

    for (int j = tid; j < DF; j += 256) {
        float w = (j < SEC0) ? inv0 : (j < SEC0 + SEC1) ? inv1 : inv2;
        z[(size_t)g * DF + j] = buf[j] * w;
    }
}

// ---------------- 5) per-(b,feature) stats ----------------
__global__ void stats_kernel() {
    int idx = blockIdx.x * 256 + threadIdx.x;
    if (idx >= BB * DF) return;
    int b = idx / DF;
    int f = idx - b * DF;
    {
        const float* zs = g_z_s + (size_t)b * NSUP * DF + f;
        float m = 0.0f;
        for (int s = 0; s < NSUP; s++) m += zs[(size_t)s * DF];
        m *= (1.0f / NSUP);
        float v = 0.0f;
        for (int s = 0; s < NSUP; s++) { float d = zs[(size_t)s * DF] - m; v += d * d; }
        v *= (1.0f / (NSUP - 1));
        g_mu_s[idx] = m;
        g_std_s[idx] = sqrtf(v) + 1e-8f;
    }
    {
        const float* zq = g_z_q + (size_t)b * NQRY * DF + f;
        float m = 0.0f;
        for (int s = 0; s < NQRY; s++) m += zq[(size_t)s * DF];
        m *= (1.0f / NQRY);
        float v = 0.0f;
        for (int s = 0; s < NQRY; s++) { float d = zq[(size_t)s * DF] - m; v += d * d; }
        v *= (1.0f / (NQRY - 1));
        g_mu_q[idx] = m;
        g_std_q[idx] = sqrtf(v) + 1e-8f;
    }
}

// ---------------- 6) center/standardize + row l2norm ----------------
__global__ void rownorm_kernel(int which) {
    __shared__ float red[256];
    int g = blockIdx.x;
    int tid = threadIdx.x;
    if (which == 0) {
        int b = g / NSUP;
        float* z = g_z_s + (size_t)g * DF;
        const float* mu = g_mu_s + (size_t)b * DF;
        float ss = 0.0f;
        for (int f = tid; f < DF; f += 256) { float v = z[f] - mu[f]; ss += v * v; }
        float S = block_reduce_sum(ss, red, tid);
        float inv = 1.0f / fmaxf(sqrtf(S), 1e-12f);
        for (int f = tid; f < DF; f += 256) z[f] = (z[f] - mu[f]) * inv;
    } else {
        int b = g / NQRY;
        float* z = g_z_q + (size_t)g * DF;
        const float* muq = g_mu_q + (size_t)b * DF;
        const float* sdq = g_std_q + (size_t)b * DF;
        const float* sds = g_std_s + (size_t)b * DF;
        float ss = 0.0f;
        for (int f = tid; f < DF; f += 256) {
            float v = (z[f] - muq[f]) / sdq[f] * sds[f];
            ss += v * v;
        }
        float S = block_reduce_sum(ss, red, tid);
        float inv = 1.0f / fmaxf(sqrtf(S), 1e-12f);
        for (int f = tid; f < DF; f += 256) {
            float v = (z[f] - muq[f]) / sdq[f] * sds[f];
            z[f] = v * inv;
        }
    }
}

// ---------------- 7) gram: K (25x25) and sim (50x25) per b ----------------
__global__ void gram_kernel() {
    int b = blockIdx.x;
    int i = blockIdx.y;   // 0..74
    int tid = threadIdx.x;
    const float* rowi = (i < NSUP)
        ? g_z_s + (size_t)(b * NSUP + i) * DF
        : g_z_q + (size_t)(b * NQRY + (i - NSUP)) * DF;
    const float* zsb = g_z_s + (size_t)b * NSUP * DF;

    float part[NSUP];
    #pragma unroll
    for (int j = 0; j < NSUP; j++) part[j] = 0.0f;
    for (int f = tid; f < DF; f += 256) {
        float a = rowi[f];
        #pragma unroll
        for (int j = 0; j < NSUP; j++) part[j] += a * zsb[(size_t)j * DF + f];
    }
    __shared__ float red[256];
    for (int j = 0; j < NSUP; j++) {
        red[tid] = part[j];
        __syncthreads();
        for (int s = 128; s > 0; s >>= 1) {
            if (tid < s) red[tid] += red[tid + s];
            __syncthreads();
        }
        if (tid == 0) g_gram[(b * 75 + i) * 25 + j] = red[0];
        __syncthreads();
    }
}

// ---------------- 8) ridge solve + output ----------------
__global__ void solve_kernel(const int* __restrict__ y_sup, float* __restrict__ out) {
    int b = blockIdx.x;
    int tid = threadIdx.x;   // 32 threads
    __shared__ float Ab[25][31];
    __shared__ float alpha[25][5];
    const float lam = 0.1f * ((float)DF / 500.0f);

    for (int idx = tid; idx < 25 * 30; idx += 32) {
        int i = idx / 30;
        int j = idx - i * 30;
        if (j < 25) {
            Ab[i][j] = g_gram[(b * 75 + i) * 25 + j] + ((i == j) ? lam : 0.0f);
        } else {
            int c = j - 25;
            Ab[i][j] = (y_sup[b * NSUP + i] == c) ? 1.0f : 0.0f;
        }
    }
    __syncthreads();
    for (int k = 0; k < 25; k++) {
        if (tid < 25 && tid != k) {
            float factor = Ab[tid][k] / Ab[k][k];
            for (int j = k; j < 30; j++) Ab[tid][j] -= factor * Ab[k][j];
        }
        __syncthreads();
    }
    for (int idx = tid; idx < 125; idx += 32) {
        int i = idx / 5;
        int c = idx - i * 5;
        alpha[i][c] = Ab[i][25 + c] / Ab[i][i];
    }
    __syncthreads();
    for (int idx = tid; idx < NQRY * NC; idx += 32) {
        int q = idx / NC;
        int c = idx - q * NC;
        float s = 0.0f;
        #pragma unroll
        for (int j = 0; j < 25; j++) s += g_gram[(b * 75 + 25 + q) * 25 + j] * alpha[j][c];
        out[((size_t)b * NQRY + q) * NC + c] = 20.0f * s;
    }
}

// ---------------- launch ----------------
extern "C" void kernel_launch(void* const* d_in, const int* in_sizes, int n_in,
                              void* d_out, int out_size) {
    const float* feats_sup   = (const float*)d_in[0];
    const float* feats_qry   = (const float*)d_in[1];
    const float* cov_reducer = (const float*)d_in[2];
    const float* w_bls       = (const float*)d_in[3];
    const float* b_bls       = (const float*)d_in[4];
    const int*   y_sup       = (const int*)d_in[5];
    float* out = (float*)d_out;

    static const size_t CS_SMEM = (size_t)CS_SMEM_FLOATS * sizeof(float);
    cudaFuncSetAttribute(covsqrt_kernel, cudaFuncAttributeMaxDynamicSharedMemorySize, (int)CS_SMEM);

    dim3 blk2d(16, 16);

    // gap
    gap_kernel<<<dim3(MS, 3), 256>>>(feats_sup, 0);
    gap_kernel<<<dim3(MQ, 3), 256>>>(feats_qry, 1);

    // projection GEMM (fp32)
    proj_gemm_kernel<<<dim3(MS, 1), blk2d>>>(feats_sup, cov_reducer, 0);
    proj_gemm_kernel<<<dim3(MQ, 1), blk2d>>>(feats_qry, cov_reducer, 1);

    // BLS GEMM on tensor cores (tf32)
    bls_mma_kernel<<<dim3(MS, 12), 256>>>(feats_sup, w_bls, b_bls, 0);
    bls_mma_kernel<<<dim3(MQ, 12), 256>>>(feats_qry, w_bls, b_bls, 1);

    // cov + Newton-Schulz sqrt
    covsqrt_kernel<<<MS, blk2d, CS_SMEM>>>(0);
    covsqrt_kernel<<<MQ, blk2d, CS_SMEM>>>(1);

    // fuse
    fuse_kernel<<<GS, 256>>>(0);
    fuse_kernel<<<GQ, 256>>>(1);

    // stats
    stats_kernel<<<(BB * DF + 255) / 256, 256>>>();

    // center + l2norm rows
    rownorm_kernel<<<GS, 256>>>(0);
    rownorm_kernel<<<GQ, 256>>>(1);

    // gram
    gram_kernel<<<dim3(BB, 75), 256>>>();

    // solve + logits
    solve_kernel<<<BB, 32>>>(y_sup, out);
}

// round 12
// speedup vs baseline: 2.5511x; 2.4586x over previous
#include <cuda_runtime.h>
#include <cuda_bf16.h>
#include <math.h>
#include <stdint.h>

// ---------------- problem constants ----------------
#define LN    2
#define NSEQ  196
#define DIM   768
#define PP    64
#define BB    2
#define NSUP  25
#define NQRY  50
#define NV    5
#define MS    500
#define MQ    1000
#define MTS   250
#define MTQ   500
#define GS    50
#define GQ    100
#define TRI   2080
#define SEC0  1536
#define SEC1  4160
#define DF    7232
#define NC    5

// ---------------- scratch ----------------
__device__ float g_gap_s[MS * DIM];
__device__ float g_gap_q[MQ * DIM];
__device__ float g_bls_s[MS * DIM];
__device__ float g_bls_q[MQ * DIM];
__device__ float g_proj_s[MS * NSEQ * PP];
__device__ float g_proj_q[MQ * NSEQ * PP];
__device__ float g_cs_s[MS * PP * PP];
__device__ float g_cs_q[MQ * PP * PP];
__device__ float g_z_s[GS * DF];
__device__ float g_z_q[GQ * DF];
__device__ float g_mu_s[BB * DF];
__device__ float g_std_s[BB * DF];
__device__ float g_mu_q[BB * DF];
__device__ float g_std_q[BB * DF];
__device__ float g_gram[BB * 75 * 25];
// bf16 copies for tensor-core BLS GEMM
__device__ __nv_bfloat16 g_ab_s[MS * NSEQ * DIM];
__device__ __nv_bfloat16 g_ab_q[MQ * NSEQ * DIM];
__device__ __nv_bfloat16 g_wtb[DIM * DIM];       // W^T: [n][k]

// ---------------- helpers ----------------
__device__ __forceinline__ float tukey_f(float x) {
    float s = (x > 0.0f ? 1.0f : 0.0f) - (x < 0.0f ? 1.0f : 0.0f);
    return s * sqrtf(fabsf(x) + 1e-8f);
}

__device__ __forceinline__ float block_reduce_sum(float v, float* red, int tid) {
    red[tid] = v;
    __syncthreads();
    for (int s = 128; s > 0; s >>= 1) {
        if (tid < s) red[tid] += red[tid + s];
        __syncthreads();
    }
    float r = red[0];
    __syncthreads();
    return r;
}

// pack two fp32 into bf16x2 word: lo = first arg in low half
__device__ __forceinline__ uint32_t pack_bf16x2(float lo, float hi) {
    uint32_t r;
    asm("cvt.rn.bf16x2.f32 %0, %1, %2;" : "=r"(r) : "f"(hi), "f"(lo));
    return r;
}

__device__ __forceinline__ void mma_bf16(float c[4], uint32_t a0, uint32_t a1,
                                         uint32_t a2, uint32_t a3,
                                         uint32_t b0, uint32_t b1) {
    asm volatile(
        "mma.sync.aligned.m16n8k16.row.col.f32.bf16.bf16.f32 "
        "{%0,%1,%2,%3}, {%4,%5,%6,%7}, {%8,%9}, {%0,%1,%2,%3};"
        : "+f"(c[0]), "+f"(c[1]), "+f"(c[2]), "+f"(c[3])
        : "r"(a0), "r"(a1), "r"(a2), "r"(a3), "r"(b0), "r"(b1));
}

// ---------------- 0a) convert feats fp32 -> bf16 (8 elems/thread) ----------------
__global__ void convert_a_kernel(const float* __restrict__ src,
                                 __nv_bfloat16* __restrict__ dst, int n8) {
    int i = blockIdx.x * 256 + threadIdx.x;
    if (i >= n8) return;
    const float4* s = (const float4*)src + (size_t)i * 2;
    float4 v0 = s[0];
    float4 v1 = s[1];
    uint4 o;
    o.x = pack_bf16x2(v0.x, v0.y);
    o.y = pack_bf16x2(v0.z, v0.w);
    o.z = pack_bf16x2(v1.x, v1.y);
    o.w = pack_bf16x2(v1.z, v1.w);
    ((uint4*)dst)[i] = o;
}

// ---------------- 0b) transpose + convert w_bls -> g_wtb [n][k] bf16 ----------------
__global__ void convert_wt_kernel(const float* __restrict__ W) {
    __shared__ float t[32][33];
    int tx = threadIdx.x, ty = threadIdx.y;          // block 32x8
    int kbase = blockIdx.y * 32;
    int nbase = blockIdx.x * 32;
    #pragma unroll
    for (int j = 0; j < 32; j += 8)
        t[ty + j][tx] = W[(size_t)(kbase + ty + j) * DIM + nbase + tx];
    __syncthreads();
    #pragma unroll
    for (int j = 0; j < 32; j += 8)
        g_wtb[(size_t)(nbase + ty + j) * DIM + kbase + tx] =
            __float2bfloat16(t[tx][ty + j]);
}

// ---------------- 1) gap = mean over N ----------------
__global__ void gap_kernel(const float* __restrict__ feat, int which) {
    float* out = which ? g_gap_q : g_gap_s;
    int mi = blockIdx.x;
    int d = blockIdx.y * 256 + threadIdx.x;
    const float* base = feat + (size_t)mi * NSEQ * DIM + d;
    float s = 0.0f;
    #pragma unroll 4
    for (int n = 0; n < NSEQ; n++) s += base[(size_t)n * DIM];
    out[(size_t)mi * DIM + d] = s * (1.0f / NSEQ);
}

// ---------------- 2a) projection GEMM (fp32) ----------------
__global__ void proj_gemm_kernel(const float* __restrict__ feat,
                                 const float* __restrict__ W,
                                 int which) {
    __shared__ float As[32][208];
    __shared__ float Ws[32][64];

    int mi = blockIdx.x;
    int tx = threadIdx.x, ty = threadIdx.y;
    int tid = ty * 16 + tx;
    const float* A = feat + (size_t)mi * NSEQ * DIM;

    float acc[13][4];
    #pragma unroll
    for (int r = 0; r < 13; r++)
        #pragma unroll
        for (int c = 0; c < 4; c++) acc[r][c] = 0.0f;

    for (int k0 = 0; k0 < DIM; k0 += 32) {
        __syncthreads();
        for (int idx = tid; idx < 1568; idx += 256) {
            int n = idx >> 3;
            int q = idx & 7;
            float4 v = *(const float4*)(A + (size_t)n * DIM + k0 + 4 * q);
            int kk = 4 * q;
            As[kk][n] = v.x; As[kk + 1][n] = v.y; As[kk + 2][n] = v.z; As[kk + 3][n] = v.w;
        }
        for (int idx = tid; idx < 512; idx += 256) {
            int kk = idx >> 4;
            int q = idx & 15;
            float4 v = *(const float4*)(W + (size_t)(k0 + kk) * PP + 4 * q);
            *(float4*)&Ws[kk][4 * q] = v;
        }
        __syncthreads();
        #pragma unroll 8
        for (int kk = 0; kk < 32; kk++) {
            float w0 = Ws[kk][tx];
            float w1 = Ws[kk][tx + 16];
            float w2 = Ws[kk][tx + 32];
            float w3 = Ws[kk][tx + 48];
            #pragma unroll
            for (int r = 0; r < 13; r++) {
                float a = As[kk][ty + 16 * r];
                acc[r][0] += a * w0;
                acc[r][1] += a * w1;
                acc[r][2] += a * w2;
                acc[r][3] += a * w3;
            }
        }
    }

    float* outp = which ? g_proj_q : g_proj_s;
    #pragma unroll
    for (int r = 0; r < 13; r++) {
        int n = ty + 16 * r;
        if (n < NSEQ) {
            #pragma unroll
            for (int c = 0; c < 4; c++)
                outp[(size_t)mi * NSEQ * PP + (size_t)n * PP + tx + 16 * c] = acc[r][c];
        }
    }
}

// ---------------- 2b) BLS GEMM: bf16 mma.sync.m16n8k16 ----------------
// bls[mi][n] = mean_m tanh( sum_k A[m][k] * W[k][n] + b[n] )
// grid = (12 n-tiles, M matrices): adjacent CTAs share the A matrix (L2 reuse).
// smem XOR-swizzle: word w of row r lives at r*32 + ((w>>2 ^ (r&7))<<2) + (w&3).
__global__ void __launch_bounds__(256, 2)
bls_bf16_kernel(const __nv_bfloat16* __restrict__ Abf,
                const __nv_bfloat16* __restrict__ Wt,
                const float* __restrict__ bias, int which) {
    __shared__ uint32_t As[208 * 32];   // 208 rows x 64 bf16 (swizzled)
    __shared__ uint32_t Ws[64 * 32];    // 64 n-rows x 64 bf16 (swizzled)
    __shared__ float colsum[4][64];

    int nt = blockIdx.x;
    int mi = blockIdx.y;
    int n0 = nt * 64;
    const __nv_bfloat16* A = Abf + (size_t)mi * NSEQ * DIM;

    int tid = threadIdx.x;
    int lane = tid & 31;
    int warp = tid >> 5;
    int wm = warp & 3;                  // M split (4)
    int wn = warp >> 2;                 // N split (2)
    int gid = lane >> 2;                // 0..7
    int tig = lane & 3;                 // 0..3

    float acc[4][4][4];
    #pragma unroll
    for (int mt = 0; mt < 4; mt++)
        #pragma unroll
        for (int nf = 0; nf < 4; nf++)
            #pragma unroll
            for (int c = 0; c < 4; c++) acc[mt][nf][c] = 0.0f;

    for (int kc = 0; kc < 12; kc++) {
        __syncthreads();
        // A chunk: 208 rows x 64 k (bf16), rows >= 196 zero. uint4 = 8 bf16.
        for (int idx = tid; idx < 1664; idx += 256) {
            int row = idx >> 3;
            int q = idx & 7;
            uint4 v = make_uint4(0u, 0u, 0u, 0u);
            if (row < NSEQ)
                v = *((const uint4*)(A + (size_t)row * DIM + kc * 64) + q);
            *(uint4*)&As[row * 32 + ((q ^ (row & 7)) << 2)] = v;
        }
        // W tile: 64 n-rows x 64 k
        for (int idx = tid; idx < 512; idx += 256) {
            int r = idx >> 3;
            int q = idx & 7;
            uint4 v = *((const uint4*)(Wt + (size_t)(n0 + r) * DIM + kc * 64) + q);
            *(uint4*)&Ws[r * 32 + ((q ^ (r & 7)) << 2)] = v;
        }
        __syncthreads();

        #pragma unroll
        for (int ks = 0; ks < 4; ks++) {
            uint32_t b0[4], b1[4];
            #pragma unroll
            for (int nf = 0; nf < 4; nf++) {
                int nc = wn * 32 + nf * 8 + gid;
                int sw = nc & 7;
                b0[nf] = Ws[nc * 32 + (((2 * ks) ^ sw) << 2) + tig];
                b1[nf] = Ws[nc * 32 + (((2 * ks + 1) ^ sw) << 2) + tig];
            }
            #pragma unroll
            for (int mt = 0; mt < 4; mt++) {
                int mtg = wm + 4 * mt;
                if (mtg < 13) {
                    int r0 = mtg * 16 + gid;
                    int r1 = r0 + 8;
                    int sw = gid;     // r0&7 == r1&7 == gid
                    uint32_t a0 = As[r0 * 32 + (((2 * ks) ^ sw) << 2) + tig];
                    uint32_t a1 = As[r1 * 32 + (((2 * ks) ^ sw) << 2) + tig];
                    uint32_t a2 = As[r0 * 32 + (((2 * ks + 1) ^ sw) << 2) + tig];
                    uint32_t a3 = As[r1 * 32 + (((2 * ks + 1) ^ sw) << 2) + tig];
                    #pragma unroll
                    for (int nf = 0; nf < 4; nf++)
                        mma_bf16(acc[mt][nf], a0, a1, a2, a3, b0[nf], b1[nf]);
                }
            }
        }
    }

    // epilogue: tanh(acc + bias) column-mean over valid rows
    #pragma unroll
    for (int nf = 0; nf < 4; nf++) {
        int cb = n0 + wn * 32 + nf * 8 + 2 * tig;
        float bv0 = bias[cb];
        float bv1 = bias[cb + 1];
        float p0 = 0.0f, p1 = 0.0f;
        #pragma unroll
        for (int mt = 0; mt < 4; mt++) {
            int mtg = wm + 4 * mt;
            if (mtg < 13) {
                int r0 = mtg * 16 + gid;
                int r1 = r0 + 8;
                if (r0 < NSEQ) {
                    p0 += tanhf(acc[mt][nf][0] + bv0);
                    p1 += tanhf(acc[mt][nf][1] + bv1);
                }
                if (r1 < NSEQ) {
                    p0 += tanhf(acc[mt][nf][2] + bv0);
                    p1 += tanhf(acc[mt][nf][3] + bv1);
                }
            }
        }
        #pragma unroll
        for (int off = 4; off <= 16; off <<= 1) {
            p0 += __shfl_xor_sync(0xffffffff, p0, off);
            p1 += __shfl_xor_sync(0xffffffff, p1, off);
        }
        if (gid == 0) {
            colsum[wm][wn * 32 + nf * 8 + 2 * tig]     = p0;
            colsum[wm][wn * 32 + nf * 8 + 2 * tig + 1] = p1;
        }
    }
    __syncthreads();
    if (tid < 64) {
        float s = colsum[0][tid] + colsum[1][tid] + colsum[2][tid] + colsum[3][tid];
        float* outp = which ? g_bls_q : g_bls_s;
        outp[(size_t)mi * DIM + n0 + tid] = s * (1.0f / NSEQ);
    }
}

// ---------------- 3) cov + Newton-Schulz matrix sqrt ----------------
#define CS_SMEM_FLOATS (NSEQ * 65 + 3 * 64 * 65 + 256 + 64)

__global__ void covsqrt_kernel(int which) {
    extern __shared__ float sh[];
    float* X = sh;
    float* Yb = X + NSEQ * 65;
    float* Zb = Yb + 64 * 65;
    float* Tb = Zb + 64 * 65;
    float* red = Tb + 64 * 65;
    float* mean = red + 256;

    const float* proj = which ? g_proj_q : g_proj_s;
    float* cs = which ? g_cs_q : g_cs_s;
    int mi = blockIdx.x;
    int tx = threadIdx.x, ty = threadIdx.y;
    int tid = ty * 16 + tx;

    for (int idx = tid; idx < NSEQ * PP; idx += 256) {
        int n = idx >> 6;
        int p = idx & 63;
        X[n * 65 + p] = proj[(size_t)mi * NSEQ * PP + idx];
    }
    __syncthreads();
    if (tid < 64) {
        float s = 0.0f;
        for (int n = 0; n < NSEQ; n++) s += X[n * 65 + tid];
        mean[tid] = s * (1.0f / NSEQ);
    }
    __syncthreads();
    for (int idx = tid; idx < NSEQ * PP; idx += 256) {
        int n = idx >> 6;
        int p = idx & 63;
        X[n * 65 + p] -= mean[p];
    }
    __syncthreads();

    float cacc[4][4];
    #pragma unroll
    for (int i = 0; i < 4; i++)
        #pragma unroll
        for (int j = 0; j < 4; j++) cacc[i][j] = 0.0f;
    for (int n = 0; n < NSEQ; n++) {
        float a[4], b[4];
        #pragma unroll
        for (int i = 0; i < 4; i++) a[i] = X[n * 65 + ty + 16 * i];
        #pragma unroll
        for (int j = 0; j < 4; j++) b[j] = X[n * 65 + tx + 16 * j];
        #pragma unroll
        for (int i = 0; i < 4; i++)
            #pragma unroll
            for (int j = 0; j < 4; j++) cacc[i][j] += a[i] * b[j];
    }
    float ss = 0.0f;
    #pragma unroll
    for (int i = 0; i < 4; i++) {
        int p = ty + 16 * i;
        #pragma unroll
        for (int j = 0; j < 4; j++) {
            int q = tx + 16 * j;
            float v = cacc[i][j] * (1.0f / 195.0f) + ((p == q) ? 1e-5f : 0.0f);
            Yb[p * 65 + q] = v;
            ss += v * v;
        }
    }
    float total = block_reduce_sum(ss, red, tid);
    float norm = sqrtf(total);
    float inv = 1.0f / (norm + 1e-8f);
    #pragma unroll
    for (int i = 0; i < 4; i++) {
        int p = ty + 16 * i;
        #pragma unroll
        for (int j = 0; j < 4; j++) {
            int q = tx + 16 * j;
            Yb[p * 65 + q] *= inv;
            Zb[p * 65 + q] = (p == q) ? 1.0f : 0.0f;
        }
    }
    __syncthreads();

    for (int it = 0; it < 3; it++) {
        float tacc[4][4];
        #pragma unroll
        for (int i = 0; i < 4; i++)
            #pragma unroll
            for (int j = 0; j < 4; j++) tacc[i][j] = 0.0f;
        for (int k = 0; k < 64; k++) {
            float a[4], b[4];
            #pragma unroll
            for (int i = 0; i < 4; i++) a[i] = Zb[(ty + 16 * i) * 65 + k];
            #pragma unroll
            for (int j = 0; j < 4; j++) b[j] = Yb[k * 65 + tx + 16 * j];
            #pragma unroll
            for (int i = 0; i < 4; i++)
                #pragma unroll
                for (int j = 0; j < 4; j++) tacc[i][j] += a[i] * b[j];
        }
        #pragma unroll
        for (int i = 0; i < 4; i++) {
            int p = ty + 16 * i;
            #pragma unroll
            for (int j = 0; j < 4; j++) {
                int q = tx + 16 * j;
                Tb[p * 65 + q] = ((p == q) ? 1.5f : 0.0f) - 0.5f * tacc[i][j];
            }
        }
        __syncthreads();
        float yacc[4][4], zacc[4][4];
        #pragma unroll
        for (int i = 0; i < 4; i++)
            #pragma unroll
            for (int j = 0; j < 4; j++) { yacc[i][j] = 0.0f; zacc[i][j] = 0.0f; }
        for (int k = 0; k < 64; k++) {
            float ya[4], tb[4], ta[4], zb2[4];
            #pragma unroll
            for (int i = 0; i < 4; i++) {
                ya[i] = Yb[(ty + 16 * i) * 65 + k];
                ta[i] = Tb[(ty + 16 * i) * 65 + k];
            }
            #pragma unroll
            for (int j = 0; j < 4; j++) {
                tb[j] = Tb[k * 65 + tx + 16 * j];
                zb2[j] = Zb[k * 65 + tx + 16 * j];
            }
            #pragma unroll
            for (int i = 0; i < 4; i++)
                #pragma unroll
                for (int j = 0; j < 4; j++) {
                    yacc[i][j] += ya[i] * tb[j];
                    zacc[i][j] += ta[i] * zb2[j];
                }
        }
        __syncthreads();
        #pragma unroll
        for (int i = 0; i < 4; i++) {
            int p = ty + 16 * i;
            #pragma unroll
            for (int j = 0; j < 4; j++) {
                int q = tx + 16 * j;
                Yb[p * 65 + q] = yacc[i][j];
                Zb[p * 65 + q] = zacc[i][j];
            }
        }
        __syncthreads();
    }

    float sc = sqrtf(norm + 1e-8f);
    #pragma unroll
    for (int i = 0; i < 4; i++) {
        int p = ty + 16 * i;
        #pragma unroll
        for (int j = 0; j < 4; j++) {
            int q = tx + 16 * j;
            cs[(size_t)mi * 4096 + p * 64 + q] = Yb[p * 65 + q] * sc;
        }
    }
}

// ---------------- 4) fuse ----------------
__global__ void fuse_kernel(int which) {
    const float* gap = which ? g_gap_q : g_gap_s;
    const float* cs = which ? g_cs_q : g_cs_s;
    const float* bls = which ? g_bls_q : g_bls_s;
    float* z = which ? g_z_q : g_z_s;
    int Mt = which ? MTQ : MTS;

    __shared__ float buf[DF];
    __shared__ float red[256];
    int g = blockIdx.x;
    int tid = threadIdx.x;
    int m0 = g * NV;

    float ss0 = 0.0f, ss1 = 0.0f, ss2 = 0.0f;

    for (int j = tid; j < SEC0; j += 256) {
        int l = j / DIM;
        int f = j - l * DIM;
        const float* src = gap + ((size_t)(l * Mt + m0)) * DIM + f;
        float v = 0.0f;
        #pragma unroll
        for (int vi = 0; vi < NV; vi++) v += src[(size_t)vi * DIM];
        v *= (1.0f / NV);
        float t = tukey_f(v);
        buf[j] = t;
        ss0 += t * t;
    }
    for (int j = tid; j < SEC1; j += 256) {
        int l = j / TRI;
        int f = j - l * TRI;
        int i = 0, rem = f;
        while (rem >= 64 - i) { rem -= 64 - i; i++; }
        int jj = i + rem;
        const float* src = cs + ((size_t)(l * Mt + m0)) * 4096 + i * 64 + jj;
        float v = 0.0f;
        #pragma unroll
        for (int vi = 0; vi < NV; vi++) v += src[(size_t)vi * 4096];
        v *= (1.0f / NV);
        float t = tukey_f(v);
        buf[SEC0 + j] = t;
        ss1 += t * t;
    }
    for (int j = tid; j < SEC0; j += 256) {
        int l = j / DIM;
        int f = j - l * DIM;
        const float* src = bls + ((size_t)(l * Mt + m0)) * DIM + f;
        float v = 0.0f;
        #pragma unroll
        for (int vi = 0; vi < NV; vi++) v += src[(size_t)vi * DIM];
        v *= (1.0f / NV);
        float t = tukey_f(v);
        buf[SEC0 + SEC1 + j] = t;
        ss2 += t * t;
    }
    __syncthreads();
    float S0 = block_reduce_sum(ss0, red, tid);
    float S1 = block_reduce_sum(ss1, red, tid);
    float S2 = block_reduce_sum(ss2, red, tid);
    float inv0 = 1.0f / fmaxf(sqrtf(S0), 1e-12f) * 1.0f;
    float inv1 = 1.0f / fmaxf(sqrtf(S1), 1e-12f) * 0.8f;
    float inv2 = 1.0f / fmaxf(sqrtf(S2), 1e-12f) * 0.1f;

    for (int j = tid; j < DF; j += 256) {
        float w = (j < SEC0) ? inv0 : (j < SEC0 + SEC1) ? inv1 : inv2;
        z[(size_t)g * DF + j] = buf[j] * w;
    }
}

// ---------------- 5) per-(b,feature) stats ----------------
__global__ void stats_kernel() {
    int idx = blockIdx.x * 256 + threadIdx.x;
    if (idx >= BB * DF) return;
    int b = idx / DF;
    int f = idx - b * DF;
    {
        const float* zs = g_z_s + (size_t)b * NSUP * DF + f;
        float m = 0.0f;
        for (int s = 0; s < NSUP; s++) m += zs[(size_t)s * DF];
        m *= (1.0f / NSUP);
        float v = 0.0f;
        for (int s = 0; s < NSUP; s++) { float d = zs[(size_t)s * DF] - m; v += d * d; }
        v *= (1.0f / (NSUP - 1));
        g_mu_s[idx] = m;
        g_std_s[idx] = sqrtf(v) + 1e-8f;
    }
    {
        const float* zq = g_z_q + (size_t)b * NQRY * DF + f;
        float m = 0.0f;
        for (int s = 0; s < NQRY; s++) m += zq[(size_t)s * DF];
        m *= (1.0f / NQRY);
        float v = 0.0f;
        for (int s = 0; s < NQRY; s++) { float d = zq[(size_t)s * DF] - m; v += d * d; }
        v *= (1.0f / (NQRY - 1));
        g_mu_q[idx] = m;
        g_std_q[idx] = sqrtf(v) + 1e-8f;
    }
}

// ---------------- 6) center/standardize + row l2norm ----------------
__global__ void rownorm_kernel(int which) {
    __shared__ float red[256];
    int g = blockIdx.x;
    int tid = threadIdx.x;
    if (which == 0) {
        int b = g / NSUP;
        float* z = g_z_s + (size_t)g * DF;
        const float* mu = g_mu_s + (size_t)b * DF;
        float ss = 0.0f;
        for (int f = tid; f < DF; f += 256) { float v = z[f] - mu[f]; ss += v * v; }
        float S = block_reduce_sum(ss, red, tid);
        float inv = 1.0f / fmaxf(sqrtf(S), 1e-12f);
        for (int f = tid; f < DF; f += 256) z[f] = (z[f] - mu[f]) * inv;
    } else {
        int b = g / NQRY;
        float* z = g_z_q + (size_t)g * DF;
        const float* muq = g_mu_q + (size_t)b * DF;
        const float* sdq = g_std_q + (size_t)b * DF;
        const float* sds = g_std_s + (size_t)b * DF;
        float ss = 0.0f;
        for (int f = tid; f < DF; f += 256) {
            float v = (z[f] - muq[f]) / sdq[f] * sds[f];
            ss += v * v;
        }
        float S = block_reduce_sum(ss, red, tid);
        float inv = 1.0f / fmaxf(sqrtf(S), 1e-12f);
        for (int f = tid; f < DF; f += 256) {
            float v = (z[f] - muq[f]) / sdq[f] * sds[f];
            z[f] = v * inv;
        }
    }
}

// ---------------- 7) gram ----------------
__global__ void gram_kernel() {
    int b = blockIdx.x;
    int i = blockIdx.y;
    int tid = threadIdx.x;
    const float* rowi = (i < NSUP)
        ? g_z_s + (size_t)(b * NSUP + i) * DF
        : g_z_q + (size_t)(b * NQRY + (i - NSUP)) * DF;
    const float* zsb = g_z_s + (size_t)b * NSUP * DF;

    float part[NSUP];
    #pragma unroll
    for (int j = 0; j < NSUP; j++) part[j] = 0.0f;
    for (int f = tid; f < DF; f += 256) {
        float a = rowi[f];
        #pragma unroll
        for (int j = 0; j < NSUP; j++) part[j] += a * zsb[(size_t)j * DF + f];
    }
    __shared__ float red[256];
    for (int j = 0; j < NSUP; j++) {
        red[tid] = part[j];
        __syncthreads();
        for (int s = 128; s > 0; s >>= 1) {
            if (tid < s) red[tid] += red[tid + s];
            __syncthreads();
        }
        if (tid == 0) g_gram[(b * 75 + i) * 25 + j] = red[0];
        __syncthreads();
    }
}

// ---------------- 8) ridge solve + output ----------------
__global__ void solve_kernel(const int* __restrict__ y_sup, float* __restrict__ out) {
    int b = blockIdx.x;
    int tid = threadIdx.x;
    __shared__ float Ab[25][31];
    __shared__ float alpha[25][5];
    const float lam = 0.1f * ((float)DF / 500.0f);

    for (int idx = tid; idx < 25 * 30; idx += 32) {
        int i = idx / 30;
        int j = idx - i * 30;
        if (j < 25) {
            Ab[i][j] = g_gram[(b * 75 + i) * 25 + j] + ((i == j) ? lam : 0.0f);
        } else {
            int c = j - 25;
            Ab[i][j] = (y_sup[b * NSUP + i] == c) ? 1.0f : 0.0f;
        }
    }
    __syncthreads();
    for (int k = 0; k < 25; k++) {
        if (tid < 25 && tid != k) {
            float factor = Ab[tid][k] / Ab[k][k];
            for (int j = k; j < 30; j++) Ab[tid][j] -= factor * Ab[k][j];
        }
        __syncthreads();
    }
    for (int idx = tid; idx < 125; idx += 32) {
        int i = idx / 5;
        int c = idx - i * 5;
        alpha[i][c] = Ab[i][25 + c] / Ab[i][i];
    }
    __syncthreads();
    for (int idx = tid; idx < NQRY * NC; idx += 32) {
        int q = idx / NC;
        int c = idx - q * NC;
        float s = 0.0f;
        #pragma unroll
        for (int j = 0; j < 25; j++) s += g_gram[(b * 75 + 25 + q) * 25 + j] * alpha[j][c];
        out[((size_t)b * NQRY + q) * NC + c] = 20.0f * s;
    }
}

// ---------------- launch ----------------
extern "C" void kernel_launch(void* const* d_in, const int* in_sizes, int n_in,
                              void* d_out, int out_size) {
    const float* feats_sup   = (const float*)d_in[0];
    const float* feats_qry   = (const float*)d_in[1];
    const float* cov_reducer = (const float*)d_in[2];
    const float* w_bls       = (const float*)d_in[3];
    const float* b_bls       = (const float*)d_in[4];
    const int*   y_sup       = (const int*)d_in[5];
    float* out = (float*)d_out;

    static const size_t CS_SMEM = (size_t)CS_SMEM_FLOATS * sizeof(float);
    cudaFuncSetAttribute(covsqrt_kernel, cudaFuncAttributeMaxDynamicSharedMemorySize, (int)CS_SMEM);

    dim3 blk2d(16, 16);

    // device pointers to bf16 scratch
    __nv_bfloat16 *ab_s, *ab_q, *wtb;
    cudaGetSymbolAddress((void**)&ab_s, g_ab_s);
    cudaGetSymbolAddress((void**)&ab_q, g_ab_q);
    cudaGetSymbolAddress((void**)&wtb, g_wtb);

    // bf16 pre-conversion
    int n8s = MS * NSEQ * DIM / 8;
    int n8q = MQ * NSEQ * DIM / 8;
    convert_a_kernel<<<(n8s + 255) / 256, 256>>>(feats_sup, ab_s, n8s);
    convert_a_kernel<<<(n8q + 255) / 256, 256>>>(feats_qry, ab_q, n8q);
    convert_wt_kernel<<<dim3(24, 24), dim3(32, 8)>>>(w_bls);

    // gap
    gap_kernel<<<dim3(MS, 3), 256>>>(feats_sup, 0);
    gap_kernel<<<dim3(MQ, 3), 256>>>(feats_qry, 1);

    // projection GEMM (fp32)
    proj_gemm_kernel<<<dim3(MS, 1), blk2d>>>(feats_sup, cov_reducer, 0);
    proj_gemm_kernel<<<dim3(MQ, 1), blk2d>>>(feats_qry, cov_reducer, 1);

    // BLS GEMM (bf16 tensor cores, n-tiles adjacent for L2 A reuse)
    bls_bf16_kernel<<<dim3(12, MS), 256>>>(ab_s, wtb, b_bls, 0);
    bls_bf16_kernel<<<dim3(12, MQ), 256>>>(ab_q, wtb, b_bls, 1);

    // cov + Newton-Schulz sqrt
    covsqrt_kernel<<<MS, blk2d, CS_SMEM>>>(0);
    covsqrt_kernel<<<MQ, blk2d, CS_SMEM>>>(1);

    // fuse
    fuse_kernel<<<GS, 256>>>(0);
    fuse_kernel<<<GQ, 256>>>(1);

    // stats
    stats_kernel<<<(BB * DF + 255) / 256, 256>>>();

    // center + l2norm rows
    rownorm_kernel<<<GS, 256>>>(0);
    rownorm_kernel<<<GQ, 256>>>(1);

    // gram
    gram_kernel<<<dim3(BB, 75), 256>>>();

    // solve + logits
    solve_kernel<<<BB, 32>>>(y_sup, out);
}

// round 14
// speedup vs baseline: 6.1209x; 2.3993x over previous
#include <cuda_runtime.h>
#include <cuda_bf16.h>
#include <math.h>
#include <stdint.h>

// ---------------- problem constants ----------------
#define LN    2
#define NSEQ  196
#define DIM   768
#define PP    64
#define BB    2
#define NSUP  25
#define NQRY  50
#define NV    5
#define MS    500
#define MQ    1000
#define MTS   250
#define MTQ   500
#define GS    50
#define GQ    100
#define TRI   2080
#define SEC0  1536
#define SEC1  4160
#define DF    7232
#define NC    5

// ---------------- scratch ----------------
__device__ float g_gap_s[MS * DIM];
__device__ float g_gap_q[MQ * DIM];
__device__ float g_bls_s[MS * DIM];
__device__ float g_bls_q[MQ * DIM];
__device__ float g_proj_s[MS * NSEQ * PP];
__device__ float g_proj_q[MQ * NSEQ * PP];
__device__ float g_cs_s[MS * PP * PP];
__device__ float g_cs_q[MQ * PP * PP];
__device__ float g_z_s[GS * DF];
__device__ float g_z_q[GQ * DF];
__device__ float g_mu_s[BB * DF];
__device__ float g_std_s[BB * DF];
__device__ float g_mu_q[BB * DF];
__device__ float g_std_q[BB * DF];
__device__ float g_gram[BB * 75 * 25];
// bf16 copies for tensor-core GEMMs
__device__ __nv_bfloat16 g_ab_s[MS * NSEQ * DIM];
__device__ __nv_bfloat16 g_ab_q[MQ * NSEQ * DIM];
__device__ __nv_bfloat16 g_wtb[DIM * DIM];        // w_bls^T: [n][k]
__device__ __nv_bfloat16 g_wp[2 * PP * DIM];      // cov_reducer^T hi/lo: [128][k]

// ---------------- helpers ----------------
__device__ __forceinline__ float tukey_f(float x) {
    float s = (x > 0.0f ? 1.0f : 0.0f) - (x < 0.0f ? 1.0f : 0.0f);
    return s * sqrtf(fabsf(x) + 1e-8f);
}

__device__ __forceinline__ float block_reduce_sum(float v, float* red, int tid) {
    red[tid] = v;
    __syncthreads();
    for (int s = 128; s > 0; s >>= 1) {
        if (tid < s) red[tid] += red[tid + s];
        __syncthreads();
    }
    float r = red[0];
    __syncthreads();
    return r;
}

__device__ __forceinline__ uint32_t smem_to_u32(const void* p) {
    uint32_t addr;
    asm("{ .reg .u64 tmp; cvta.to.shared.u64 tmp, %1; cvt.u32.u64 %0, tmp; }"
        : "=r"(addr) : "l"(p));
    return addr;
}

__device__ __forceinline__ void cp_async16(uint32_t dst, const void* src) {
    asm volatile("cp.async.cg.shared.global [%0], [%1], 16;" :: "r"(dst), "l"(src));
}
__device__ __forceinline__ void cp_commit() {
    asm volatile("cp.async.commit_group;" ::: "memory");
}
template <int N>
__device__ __forceinline__ void cp_wait() {
    asm volatile("cp.async.wait_group %0;" :: "n"(N) : "memory");
}

__device__ __forceinline__ void mma_bf16(float c[4], uint32_t a0, uint32_t a1,
                                         uint32_t a2, uint32_t a3,
                                         uint32_t b0, uint32_t b1) {
    asm volatile(
        "mma.sync.aligned.m16n8k16.row.col.f32.bf16.bf16.f32 "
        "{%0,%1,%2,%3}, {%4,%5,%6,%7}, {%8,%9}, {%0,%1,%2,%3};"
        : "+f"(c[0]), "+f"(c[1]), "+f"(c[2]), "+f"(c[3])
        : "r"(a0), "r"(a1), "r"(a2), "r"(a3), "r"(b0), "r"(b1));
}

// ---------------- 0a) fused convert fp32->bf16 + gap (one read of feats) ----------------
__global__ void convert_gap_kernel(const float* __restrict__ feat,
                                   __nv_bfloat16* __restrict__ dst, int which) {
    float* gap = which ? g_gap_q : g_gap_s;
    int mi = blockIdx.x;
    int d = blockIdx.y * 256 + threadIdx.x;
    const float* src = feat + (size_t)mi * NSEQ * DIM + d;
    __nv_bfloat16* o = dst + (size_t)mi * NSEQ * DIM + d;
    float s = 0.0f;
    #pragma unroll 4
    for (int n = 0; n < NSEQ; n++) {
        float v = src[(size_t)n * DIM];
        s += v;
        o[(size_t)n * DIM] = __float2bfloat16(v);
    }
    gap[(size_t)mi * DIM + d] = s * (1.0f / NSEQ);
}

// ---------------- 0b) transpose + convert w_bls -> g_wtb [n][k] bf16 ----------------
__global__ void convert_wt_kernel(const float* __restrict__ W) {
    __shared__ float t[32][33];
    int tx = threadIdx.x, ty = threadIdx.y;          // block 32x8
    int kbase = blockIdx.y * 32;
    int nbase = blockIdx.x * 32;
    #pragma unroll
    for (int j = 0; j < 32; j += 8)
        t[ty + j][tx] = W[(size_t)(kbase + ty + j) * DIM + nbase + tx];
    __syncthreads();
    #pragma unroll
    for (int j = 0; j < 32; j += 8)
        g_wtb[(size_t)(nbase + ty + j) * DIM + kbase + tx] =
            __float2bfloat16(t[tx][ty + j]);
}

// ---------------- 0c) transpose cov_reducer -> hi/lo bf16 [128][k] ----------------
__global__ void convert_wp_kernel(const float* __restrict__ R) {
    __shared__ float t[32][33];
    int tx = threadIdx.x, ty = threadIdx.y;          // block 32x8
    int kbase = blockIdx.y * 32;
    int nbase = blockIdx.x * 32;                     // blockIdx.x in {0,1}
    #pragma unroll
    for (int j = 0; j < 32; j += 8)
        t[ty + j][tx] = R[(size_t)(kbase + ty + j) * PP + nbase + tx];
    __syncthreads();
    #pragma unroll
    for (int j = 0; j < 32; j += 8) {
        int n = nbase + ty + j;
        int k = kbase + tx;
        float v = t[tx][ty + j];
        __nv_bfloat16 h = __float2bfloat16(v);
        float lo = v - __bfloat162float(h);
        g_wp[(size_t)n * DIM + k] = h;
        g_wp[(size_t)(PP + n) * DIM + k] = __float2bfloat16(lo);
    }
}

// ---------------- 2a) projection GEMM: bf16 mma, W split hi/lo, cp.async 2-stage ----------------
// proj[mi][row][p] = sum_k A[row][k] * (Whi[k][p] + Wlo[k][p]),  fp32 accum.
#define PROJ_SMEM_WORDS (2 * 6656 + 2 * 4096)
#define PROJ_SMEM_BYTES (PROJ_SMEM_WORDS * 4)

__global__ void __launch_bounds__(256, 2)
proj_bf16_kernel(const __nv_bfloat16* __restrict__ Abf,
                 const __nv_bfloat16* __restrict__ Wp, int which) {
    extern __shared__ uint32_t sh[];
    uint32_t* As = sh;                 // 2 x [208 rows x 32 words] (swizzled)
    uint32_t* Ws = sh + 13312;         // 2 x [128 rows x 32 words]
    uint32_t as_b = smem_to_u32(As);
    uint32_t ws_b = smem_to_u32(Ws);

    int mi = blockIdx.x;
    const __nv_bfloat16* A = Abf + (size_t)mi * NSEQ * DIM;

    int tid = threadIdx.x;
    int lane = tid & 31;
    int warp = tid >> 5;
    int wm = warp & 3;
    int wn = warp >> 2;
    int gid = lane >> 2;
    int tig = lane & 3;

    // zero-pad A rows 196..207 (both buffers)
    for (int i = tid; i < 768; i += 256) {
        int buf = i >= 384;
        As[buf * 6656 + 6272 + (i & 383)] = 0u;
    }

    auto issue = [&](int kc, int buf) {
        for (int idx = tid; idx < 1568; idx += 256) {
            int row = idx >> 3;
            int q = idx & 7;
            uint32_t dst = as_b + (buf * 6656 + row * 32 + ((q ^ (row & 7)) << 2)) * 4;
            cp_async16(dst, A + (size_t)row * DIM + kc * 64 + q * 8);
        }
        for (int idx = tid; idx < 1024; idx += 256) {
            int r = idx >> 3;                 // 0..127 (hi rows 0-63, lo rows 64-127)
            int q = idx & 7;
            uint32_t dst = ws_b + (buf * 4096 + r * 32 + ((q ^ (r & 7)) << 2)) * 4;
            cp_async16(dst, Wp + (size_t)r * DIM + kc * 64 + q * 8);
        }
        cp_commit();
    };

    float acc[4][4][4];
    #pragma unroll
    for (int mt = 0; mt < 4; mt++)
        #pragma unroll
        for (int nf = 0; nf < 4; nf++)
            #pragma unroll
            for (int c = 0; c < 4; c++) acc[mt][nf][c] = 0.0f;

    issue(0, 0);
    for (int kc = 0; kc < 12; kc++) {
        int buf = kc & 1;
        if (kc < 11) { issue(kc + 1, buf ^ 1); cp_wait<1>(); }
        else cp_wait<0>();
        __syncthreads();
        uint32_t* Asb = As + buf * 6656;
        uint32_t* Wsb = Ws + buf * 4096;

        #pragma unroll
        for (int ks = 0; ks < 4; ks++) {
            uint32_t bh0[4], bh1[4], bl0[4], bl1[4];
            #pragma unroll
            for (int nf = 0; nf < 4; nf++) {
                int nc = wn * 32 + nf * 8 + gid;
                int sw = nc & 7;
                bh0[nf] = Wsb[nc * 32 + (((2 * ks) ^ sw) << 2) + tig];
                bh1[nf] = Wsb[nc * 32 + (((2 * ks + 1) ^ sw) << 2) + tig];
                bl0[nf] = Wsb[(64 + nc) * 32 + (((2 * ks) ^ sw) << 2) + tig];
                bl1[nf] = Wsb[(64 + nc) * 32 + (((2 * ks + 1) ^ sw) << 2) + tig];
            }
            #pragma unroll
            for (int mt = 0; mt < 4; mt++) {
                int mtg = wm + 4 * mt;
                if (mtg < 13) {
                    int r0 = mtg * 16 + gid;
                    int r1 = r0 + 8;
                    int sw = gid;
                    uint32_t a0 = Asb[r0 * 32 + (((2 * ks) ^ sw) << 2) + tig];
                    uint32_t a1 = Asb[r1 * 32 + (((2 * ks) ^ sw) << 2) + tig];
                    uint32_t a2 = Asb[r0 * 32 + (((2 * ks + 1) ^ sw) << 2) + tig];
                    uint32_t a3 = Asb[r1 * 32 + (((2 * ks + 1) ^ sw) << 2) + tig];
                    #pragma unroll
                    for (int nf = 0; nf < 4; nf++) {
                        mma_bf16(acc[mt][nf], a0, a1, a2, a3, bh0[nf], bh1[nf]);
                        mma_bf16(acc[mt][nf], a0, a1, a2, a3, bl0[nf], bl1[nf]);
                    }
                }
            }
        }
        __syncthreads();
    }

    // epilogue: direct fp32 writes
    float* outp = (which ? g_proj_q : g_proj_s) + (size_t)mi * NSEQ * PP;
    #pragma unroll
    for (int nf = 0; nf < 4; nf++) {
        int cb = wn * 32 + nf * 8 + 2 * tig;
        #pragma unroll
        for (int mt = 0; mt < 4; mt++) {
            int mtg = wm + 4 * mt;
            if (mtg < 13) {
                int r0 = mtg * 16 + gid;
                int r1 = r0 + 8;
                if (r0 < NSEQ) {
                    outp[(size_t)r0 * PP + cb] = acc[mt][nf][0];
                    outp[(size_t)r0 * PP + cb + 1] = acc[mt][nf][1];
                }
                if (r1 < NSEQ) {
                    outp[(size_t)r1 * PP + cb] = acc[mt][nf][2];
                    outp[(size_t)r1 * PP + cb + 1] = acc[mt][nf][3];
                }
            }
        }
    }
}

// ---------------- 2b) BLS GEMM: bf16 mma, cp.async 2-stage ----------------
#define BLS_SMEM_WORDS (2 * 6656 + 2 * 2048 + 256)
#define BLS_SMEM_BYTES (BLS_SMEM_WORDS * 4)

__global__ void __launch_bounds__(256, 2)
bls_bf16_kernel(const __nv_bfloat16* __restrict__ Abf,
                const __nv_bfloat16* __restrict__ Wt,
                const float* __restrict__ bias, int which) {
    extern __shared__ uint32_t sh[];
    uint32_t* As = sh;                 // 2 x [208 x 32]
    uint32_t* Ws = sh + 13312;         // 2 x [64 x 32]
    float (*colsum)[64] = (float(*)[64])(sh + 13312 + 4096);
    uint32_t as_b = smem_to_u32(As);
    uint32_t ws_b = smem_to_u32(Ws);

    int nt = blockIdx.x;
    int mi = blockIdx.y;
    int n0 = nt * 64;
    const __nv_bfloat16* A = Abf + (size_t)mi * NSEQ * DIM;

    int tid = threadIdx.x;
    int lane = tid & 31;
    int warp = tid >> 5;
    int wm = warp & 3;
    int wn = warp >> 2;
    int gid = lane >> 2;
    int tig = lane & 3;

    for (int i = tid; i < 768; i += 256) {
        int buf = i >= 384;
        As[buf * 6656 + 6272 + (i & 383)] = 0u;
    }

    auto issue = [&](int kc, int buf) {
        for (int idx = tid; idx < 1568; idx += 256) {
            int row = idx >> 3;
            int q = idx & 7;
            uint32_t dst = as_b + (buf * 6656 + row * 32 + ((q ^ (row & 7)) << 2)) * 4;
            cp_async16(dst, A + (size_t)row * DIM + kc * 64 + q * 8);
        }
        for (int idx = tid; idx < 512; idx += 256) {
            int r = idx >> 3;
            int q = idx & 7;
            uint32_t dst = ws_b + (buf * 2048 + r * 32 + ((q ^ (r & 7)) << 2)) * 4;
            cp_async16(dst, Wt + (size_t)(n0 + r) * DIM + kc * 64 + q * 8);
        }
        cp_commit();
    };

    float acc[4][4][4];
    #pragma unroll
    for (int mt = 0; mt < 4; mt++)
        #pragma unroll
        for (int nf = 0; nf < 4; nf++)
            #pragma unroll
            for (int c = 0; c < 4; c++) acc[mt][nf][c] = 0.0f;

    issue(0, 0);
    for (int kc = 0; kc < 12; kc++) {
        int buf = kc & 1;
        if (kc < 11) { issue(kc + 1, buf ^ 1); cp_wait<1>(); }
        else cp_wait<0>();
        __syncthreads();
        uint32_t* Asb = As + buf * 6656;
        uint32_t* Wsb = Ws + buf * 2048;

        #pragma unroll
        for (int ks = 0; ks < 4; ks++) {
            uint32_t b0[4], b1[4];
            #pragma unroll
            for (int nf = 0; nf < 4; nf++) {
                int nc = wn * 32 + nf * 8 + gid;
                int sw = nc & 7;
                b0[nf] = Wsb[nc * 32 + (((2 * ks) ^ sw) << 2) + tig];
                b1[nf] = Wsb[nc * 32 + (((2 * ks + 1) ^ sw) << 2) + tig];
            }
            #pragma unroll
            for (int mt = 0; mt < 4; mt++) {
                int mtg = wm + 4 * mt;
                if (mtg < 13) {
                    int r0 = mtg * 16 + gid;
                    int r1 = r0 + 8;
                    int sw = gid;
                    uint32_t a0 = Asb[r0 * 32 + (((2 * ks) ^ sw) << 2) + tig];
                    uint32_t a1 = Asb[r1 * 32 + (((2 * ks) ^ sw) << 2) + tig];
                    uint32_t a2 = Asb[r0 * 32 + (((2 * ks + 1) ^ sw) << 2) + tig];
                    uint32_t a3 = Asb[r1 * 32 + (((2 * ks + 1) ^ sw) << 2) + tig];
                    #pragma unroll
                    for (int nf = 0; nf < 4; nf++)
                        mma_bf16(acc[mt][nf], a0, a1, a2, a3, b0[nf], b1[nf]);
                }
            }
        }
        __syncthreads();
    }

    // epilogue: tanh(acc + bias) column-mean over valid rows
    #pragma unroll
    for (int nf = 0; nf < 4; nf++) {
        int cb = n0 + wn * 32 + nf * 8 + 2 * tig;
        float bv0 = bias[cb];
        float bv1 = bias[cb + 1];
        float p0 = 0.0f, p1 = 0.0f;
        #pragma unroll
        for (int mt = 0; mt < 4; mt++) {
            int mtg = wm + 4 * mt;
            if (mtg < 13) {
                int r0 = mtg * 16 + gid;
                int r1 = r0 + 8;
                if (r0 < NSEQ) {
                    p0 += tanhf(acc[mt][nf][0] + bv0);
                    p1 += tanhf(acc[mt][nf][1] + bv1);
                }
                if (r1 < NSEQ) {
                    p0 += tanhf(acc[mt][nf][2] + bv0);
                    p1 += tanhf(acc[mt][nf][3] + bv1);
                }
            }
        }
        #pragma unroll
        for (int off = 4; off <= 16; off <<= 1) {
            p0 += __shfl_xor_sync(0xffffffff, p0, off);
            p1 += __shfl_xor_sync(0xffffffff, p1, off);
        }
        if (gid == 0) {
            colsum[wm][wn * 32 + nf * 8 + 2 * tig]     = p0;
            colsum[wm][wn * 32 + nf * 8 + 2 * tig + 1] = p1;
        }
    }
    __syncthreads();
    if (tid < 64) {
        float s = colsum[0][tid] + colsum[1][tid] + colsum[2][tid] + colsum[3][tid];
        float* outp = which ? g_bls_q : g_bls_s;
        outp[(size_t)mi * DIM + n0 + tid] = s * (1.0f / NSEQ);
    }
}

// ---------------- 3) cov + Newton-Schulz matrix sqrt ----------------
#define CS_SMEM_FLOATS (NSEQ * 65 + 3 * 64 * 65 + 256 + 64)

__global__ void covsqrt_kernel(int which) {
    extern __shared__ float fsh[];
    float* X = fsh;
    float* Yb = X + NSEQ * 65;
    float* Zb = Yb + 64 * 65;
    float* Tb = Zb + 64 * 65;
    float* red = Tb + 64 * 65;
    float* mean = red + 256;

    const float* proj = which ? g_proj_q : g_proj_s;
    float* cs = which ? g_cs_q : g_cs_s;
    int mi = blockIdx.x;
    int tx = threadIdx.x, ty = threadIdx.y;
    int tid = ty * 16 + tx;

    for (int idx = tid; idx < NSEQ * PP; idx += 256) {
        int n = idx >> 6;
        int p = idx & 63;
        X[n * 65 + p] = proj[(size_t)mi * NSEQ * PP + idx];
    }
    __syncthreads();
    if (tid < 64) {
        float s = 0.0f;
        for (int n = 0; n < NSEQ; n++) s += X[n * 65 + tid];
        mean[tid] = s * (1.0f / NSEQ);
    }
    __syncthreads();
    for (int idx = tid; idx < NSEQ * PP; idx += 256) {
        int n = idx >> 6;
        int p = idx & 63;
        X[n * 65 + p] -= mean[p];
    }
    __syncthreads();

    float cacc[4][4];
    #pragma unroll
    for (int i = 0; i < 4; i++)
        #pragma unroll
        for (int j = 0; j < 4; j++) cacc[i][j] = 0.0f;
    for (int n = 0; n < NSEQ; n++) {
        float a[4], b[4];
        #pragma unroll
        for (int i = 0; i < 4; i++) a[i] = X[n * 65 + ty + 16 * i];
        #pragma unroll
        for (int j = 0; j < 4; j++) b[j] = X[n * 65 + tx + 16 * j];
        #pragma unroll
        for (int i = 0; i < 4; i++)
            #pragma unroll
            for (int j = 0; j < 4; j++) cacc[i][j] += a[i] * b[j];
    }
    float ss = 0.0f;
    #pragma unroll
    for (int i = 0; i < 4; i++) {
        int p = ty + 16 * i;
        #pragma unroll
        for (int j = 0; j < 4; j++) {
            int q = tx + 16 * j;
            float v = cacc[i][j] * (1.0f / 195.0f) + ((p == q) ? 1e-5f : 0.0f);
            Yb[p * 65 + q] = v;
            ss += v * v;
        }
    }
    float total = block_reduce_sum(ss, red, tid);
    float norm = sqrtf(total);
    float inv = 1.0f / (norm + 1e-8f);
    #pragma unroll
    for (int i = 0; i < 4; i++) {
        int p = ty + 16 * i;
        #pragma unroll
        for (int j = 0; j < 4; j++) {
            int q = tx + 16 * j;
            Yb[p * 65 + q] *= inv;
            Zb[p * 65 + q] = (p == q) ? 1.0f : 0.0f;
        }
    }
    __syncthreads();

    for (int it = 0; it < 3; it++) {
        float tacc[4][4];
        #pragma unroll
        for (int i = 0; i < 4; i++)
            #pragma unroll
            for (int j = 0; j < 4; j++) tacc[i][j] = 0.0f;
        for (int k = 0; k < 64; k++) {
            float a[4], b[4];
            #pragma unroll
            for (int i = 0; i < 4; i++) a[i] = Zb[(ty + 16 * i) * 65 + k];
            #pragma unroll
            for (int j = 0; j < 4; j++) b[j] = Yb[k * 65 + tx + 16 * j];
            #pragma unroll
            for (int i = 0; i < 4; i++)
                #pragma unroll
                for (int j = 0; j < 4; j++) tacc[i][j] += a[i] * b[j];
        }
        #pragma unroll
        for (int i = 0; i < 4; i++) {
            int p = ty + 16 * i;
            #pragma unroll
            for (int j = 0; j < 4; j++) {
                int q = tx + 16 * j;
                Tb[p * 65 + q] = ((p == q) ? 1.5f : 0.0f) - 0.5f * tacc[i][j];
            }
        }
        __syncthreads();
        float yacc[4][4], zacc[4][4];
        #pragma unroll
        for (int i = 0; i < 4; i++)
            #pragma unroll
            for (int j = 0; j < 4; j++) { yacc[i][j] = 0.0f; zacc[i][j] = 0.0f; }
        for (int k = 0; k < 64; k++) {
            float ya[4], tb[4], ta[4], zb2[4];
            #pragma unroll
            for (int i = 0; i < 4; i++) {
                ya[i] = Yb[(ty + 16 * i) * 65 + k];
                ta[i] = Tb[(ty + 16 * i) * 65 + k];
            }
            #pragma unroll
            for (int j = 0; j < 4; j++) {
                tb[j] = Tb[k * 65 + tx + 16 * j];
                zb2[j] = Zb[k * 65 + tx + 16 * j];
            }
            #pragma unroll
            for (int i = 0; i < 4; i++)
                #pragma unroll
                for (int j = 0; j < 4; j++) {
                    yacc[i][j] += ya[i] * tb[j];
                    zacc[i][j] += ta[i] * zb2[j];
                }
        }
        __syncthreads();
        #pragma unroll
        for (int i = 0; i < 4; i++) {
            int p = ty + 16 * i;
            #pragma unroll
            for (int j = 0; j < 4; j++) {
                int q = tx + 16 * j;
                Yb[p * 65 + q] = yacc[i][j];
                Zb[p * 65 + q] = zacc[i][j];
            }
        }
        __syncthreads();
    }

    float sc = sqrtf(norm + 1e-8f);
    #pragma unroll
    for (int i = 0; i < 4; i++) {
        int p = ty + 16 * i;
        #pragma unroll
        for (int j = 0; j < 4; j++) {
            int q = tx + 16 * j;
            cs[(size_t)mi * 4096 + p * 64 + q] = Yb[p * 65 + q] * sc;
        }
    }
}

// ---------------- 4) fuse ----------------
__global__ void fuse_kernel(int which) {
    const float* gap = which ? g_gap_q : g_gap_s;
    const float* cs = which ? g_cs_q : g_cs_s;
    const float* bls = which ? g_bls_q : g_bls_s;
    float* z = which ? g_z_q : g_z_s;
    int Mt = which ? MTQ : MTS;

    __shared__ float buf[DF];
    __shared__ float red[256];
    int g = blockIdx.x;
    int tid = threadIdx.x;
    int m0 = g * NV;

    float ss0 = 0.0f, ss1 = 0.0f, ss2 = 0.0f;

    for (int j = tid; j < SEC0; j += 256) {
        int l = j / DIM;
        int f = j - l * DIM;
        const float* src = gap + ((size_t)(l * Mt + m0)) * DIM + f;
        float v = 0.0f;
        #pragma unroll
        for (int vi = 0; vi < NV; vi++) v += src[(size_t)vi * DIM];
        v *= (1.0f / NV);
        float t = tukey_f(v);
        buf[j] = t;
        ss0 += t * t;
    }
    for (int j = tid; j < SEC1; j += 256) {
        int l = j / TRI;
        int f = j - l * TRI;
        int i = 0, rem = f;
        while (rem >= 64 - i) { rem -= 64 - i; i++; }
        int jj = i + rem;
        const float* src = cs + ((size_t)(l * Mt + m0)) * 4096 + i * 64 + jj;
        float v = 0.0f;
        #pragma unroll
        for (int vi = 0; vi < NV; vi++) v += src[(size_t)vi * 4096];
        v *= (1.0f / NV);
        float t = tukey_f(v);
        buf[SEC0 + j] = t;
        ss1 += t * t;
    }
    for (int j = tid; j < SEC0; j += 256) {
        int l = j / DIM;
        int f = j - l * DIM;
        const float* src = bls + ((size_t)(l * Mt + m0)) * DIM + f;
        float v = 0.0f;
        #pragma unroll
        for (int vi = 0; vi < NV; vi++) v += src[(size_t)vi * DIM];
        v *= (1.0f / NV);
        float t = tukey_f(v);
        buf[SEC0 + SEC1 + j] = t;
        ss2 += t * t;
    }
    __syncthreads();
    float S0 = block_reduce_sum(ss0, red, tid);
    float S1 = block_reduce_sum(ss1, red, tid);
    float S2 = block_reduce_sum(ss2, red, tid);
    float inv0 = 1.0f / fmaxf(sqrtf(S0), 1e-12f) * 1.0f;
    float inv1 = 1.0f / fmaxf(sqrtf(S1), 1e-12f) * 0.8f;
    float inv2 = 1.0f / fmaxf(sqrtf(S2), 1e-12f) * 0.1f;

    for (int j = tid; j < DF; j += 256) {
        float w = (j < SEC0) ? inv0 : (j < SEC0 + SEC1) ? inv1 : inv2;
        z[(size_t)g * DF + j] = buf[j] * w;
    }
}

// ---------------- 5) per-(b,feature) stats ----------------
__global__ void stats_kernel() {
    int idx = blockIdx.x * 256 + threadIdx.x;
    if (idx >= BB * DF) return;
    int b = idx / DF;
    int f = idx - b * DF;
    {
        const float* zs = g_z_s + (size_t)b * NSUP * DF + f;
        float m = 0.0f;
        for (int s = 0; s < NSUP; s++) m += zs[(size_t)s * DF];
        m *= (1.0f / NSUP);
        float v = 0.0f;
        for (int s = 0; s < NSUP; s++) { float d = zs[(size_t)s * DF] - m; v += d * d; }
        v *= (1.0f / (NSUP - 1));
        g_mu_s[idx] = m;
        g_std_s[idx] = sqrtf(v) + 1e-8f;
    }
    {
        const float* zq = g_z_q + (size_t)b * NQRY * DF + f;
        float m = 0.0f;
        for (int s = 0; s < NQRY; s++) m += zq[(size_t)s * DF];
        m *= (1.0f / NQRY);
        float v = 0.0f;
        for (int s = 0; s < NQRY; s++) { float d = zq[(size_t)s * DF] - m; v += d * d; }
        v *= (1.0f / (NQRY - 1));
        g_mu_q[idx] = m;
        g_std_q[idx] = sqrtf(v) + 1e-8f;
    }
}

// ---------------- 6) center/standardize + row l2norm ----------------
__global__ void rownorm_kernel(int which) {
    __shared__ float red[256];
    int g = blockIdx.x;
    int tid = threadIdx.x;
    if (which == 0) {
        int b = g / NSUP;
        float* z = g_z_s + (size_t)g * DF;
        const float* mu = g_mu_s + (size_t)b * DF;
        float ss = 0.0f;
        for (int f = tid; f < DF; f += 256) { float v = z[f] - mu[f]; ss += v * v; }
        float S = block_reduce_sum(ss, red, tid);
        float inv = 1.0f / fmaxf(sqrtf(S), 1e-12f);
        for (int f = tid; f < DF; f += 256) z[f] = (z[f] - mu[f]) * inv;
    } else {
        int b = g / NQRY;
        float* z = g_z_q + (size_t)g * DF;
        const float* muq = g_mu_q + (size_t)b * DF;
        const float* sdq = g_std_q + (size_t)b * DF;
        const float* sds = g_std_s + (size_t)b * DF;
        float ss = 0.0f;
        for (int f = tid; f < DF; f += 256) {
            float v = (z[f] - muq[f]) / sdq[f] * sds[f];
            ss += v * v;
        }
        float S = block_reduce_sum(ss, red, tid);
        float inv = 1.0f / fmaxf(sqrtf(S), 1e-12f);
        for (int f = tid; f < DF; f += 256) {
            float v = (z[f] - muq[f]) / sdq[f] * sds[f];
            z[f] = v * inv;
        }
    }
}

// ---------------- 7) gram ----------------
__global__ void gram_kernel() {
    int b = blockIdx.x;
    int i = blockIdx.y;
    int tid = threadIdx.x;
    const float* rowi = (i < NSUP)
        ? g_z_s + (size_t)(b * NSUP + i) * DF
        : g_z_q + (size_t)(b * NQRY + (i - NSUP)) * DF;
    const float* zsb = g_z_s + (size_t)b * NSUP * DF;

    float part[NSUP];
    #pragma unroll
    for (int j = 0; j < NSUP; j++) part[j] = 0.0f;
    for (int f = tid; f < DF; f += 256) {
        float a = rowi[f];
        #pragma unroll
        for (int j = 0; j < NSUP; j++) part[j] += a * zsb[(size_t)j * DF + f];
    }
    __shared__ float red[256];
    for (int j = 0; j < NSUP; j++) {
        red[tid] = part[j];
        __syncthreads();
        for (int s = 128; s > 0; s >>= 1) {
            if (tid < s) red[tid] += red[tid + s];
            __syncthreads();
        }
        if (tid == 0) g_gram[(b * 75 + i) * 25 + j] = red[0];
        __syncthreads();
    }
}

// ---------------- 8) ridge solve + output ----------------
__global__ void solve_kernel(const int* __restrict__ y_sup, float* __restrict__ out) {
    int b = blockIdx.x;
    int tid = threadIdx.x;
    __shared__ float Ab[25][31];
    __shared__ float alpha[25][5];
    const float lam = 0.1f * ((float)DF / 500.0f);

    for (int idx = tid; idx < 25 * 30; idx += 32) {
        int i = idx / 30;
        int j = idx - i * 30;
        if (j < 25) {
            Ab[i][j] = g_gram[(b * 75 + i) * 25 + j] + ((i == j) ? lam : 0.0f);
        } else {
            int c = j - 25;
            Ab[i][j] = (y_sup[b * NSUP + i] == c) ? 1.0f : 0.0f;
        }
    }
    __syncthreads();
    for (int k = 0; k < 25; k++) {
        if (tid < 25 && tid != k) {
            float factor = Ab[tid][k] / Ab[k][k];
            for (int j = k; j < 30; j++) Ab[tid][j] -= factor * Ab[k][j];
        }
        __syncthreads();
    }
    for (int idx = tid; idx < 125; idx += 32) {
        int i = idx / 5;
        int c = idx - i * 5;
        alpha[i][c] = Ab[i][25 + c] / Ab[i][i];
    }
    __syncthreads();
    for (int idx = tid; idx < NQRY * NC; idx += 32) {
        int q = idx / NC;
        int c = idx - q * NC;
        float s = 0.0f;
        #pragma unroll
        for (int j = 0; j < 25; j++) s += g_gram[(b * 75 + 25 + q) * 25 + j] * alpha[j][c];
        out[((size_t)b * NQRY + q) * NC + c] = 20.0f * s;
    }
}

// ---------------- launch ----------------
extern "C" void kernel_launch(void* const* d_in, const int* in_sizes, int n_in,
                              void* d_out, int out_size) {
    const float* feats_sup   = (const float*)d_in[0];
    const float* feats_qry   = (const float*)d_in[1];
    const float* cov_reducer = (const float*)d_in[2];
    const float* w_bls       = (const float*)d_in[3];
    const float* b_bls       = (const float*)d_in[4];
    const int*   y_sup       = (const int*)d_in[5];
    float* out = (float*)d_out;

    static const size_t CS_SMEM = (size_t)CS_SMEM_FLOATS * sizeof(float);
    cudaFuncSetAttribute(covsqrt_kernel, cudaFuncAttributeMaxDynamicSharedMemorySize, (int)CS_SMEM);
    cudaFuncSetAttribute(bls_bf16_kernel, cudaFuncAttributeMaxDynamicSharedMemorySize, BLS_SMEM_BYTES);
    cudaFuncSetAttribute(proj_bf16_kernel, cudaFuncAttributeMaxDynamicSharedMemorySize, PROJ_SMEM_BYTES);

    dim3 blk2d(16, 16);

    __nv_bfloat16 *ab_s, *ab_q, *wtb, *wp;
    cudaGetSymbolAddress((void**)&ab_s, g_ab_s);
    cudaGetSymbolAddress((void**)&ab_q, g_ab_q);
    cudaGetSymbolAddress((void**)&wtb, g_wtb);
    cudaGetSymbolAddress((void**)&wp, g_wp);

    // fused bf16 convert + gap (one read of feats)
    convert_gap_kernel<<<dim3(MS, 3), 256>>>(feats_sup, ab_s, 0);
    convert_gap_kernel<<<dim3(MQ, 3), 256>>>(feats_qry, ab_q, 1);
    convert_wt_kernel<<<dim3(24, 24), dim3(32, 8)>>>(w_bls);
    convert_wp_kernel<<<dim3(2, 24), dim3(32, 8)>>>(cov_reducer);

    // projection GEMM (bf16 tensor cores, W hi/lo split)
    proj_bf16_kernel<<<MS, 256, PROJ_SMEM_BYTES>>>(ab_s, wp, 0);
    proj_bf16_kernel<<<MQ, 256, PROJ_SMEM_BYTES>>>(ab_q, wp, 1);

    // BLS GEMM (bf16 tensor cores, double-buffered cp.async)
    bls_bf16_kernel<<<dim3(12, MS), 256, BLS_SMEM_BYTES>>>(ab_s, wtb, b_bls, 0);
    bls_bf16_kernel<<<dim3(12, MQ), 256, BLS_SMEM_BYTES>>>(ab_q, wtb, b_bls, 1);

    // cov + Newton-Schulz sqrt
    covsqrt_kernel<<<MS, blk2d, CS_SMEM>>>(0);
    covsqrt_kernel<<<MQ, blk2d, CS_SMEM>>>(1);

    // fuse
    fuse_kernel<<<GS, 256>>>(0);
    fuse_kernel<<<GQ, 256>>>(1);

    // stats
    stats_kernel<<<(BB * DF + 255) / 256, 256>>>();

    // center + l2norm rows
    rownorm_kernel<<<GS, 256>>>(0);
    rownorm_kernel<<<GQ, 256>>>(1);

    // gram
    gram_kernel<<<dim3(BB, 75), 256>>>();

    // solve + logits
    solve_kernel<<<BB, 32>>>(y_sup, out);
}

// round 16
// speedup vs baseline: 6.3420x; 1.0361x over previous
#include <cuda_runtime.h>
#include <cuda_bf16.h>
#include <math.h>
#include <stdint.h>

// ---------------- problem constants ----------------
#define LN    2
#define NSEQ  196
#define DIM   768
#define PP    64
#define BB    2
#define NSUP  25
#define NQRY  50
#define NV    5
#define MS    500
#define MQ    1000
#define MTS   250
#define MTQ   500
#define GS    50
#define GQ    100
#define TRI   2080
#define SEC0  1536
#define SEC1  4160
#define DF    7232
#define NC    5

// ---------------- scratch ----------------
__device__ float g_gap_s[MS * DIM];
__device__ float g_gap_q[MQ * DIM];
__device__ float g_bls_s[MS * DIM];
__device__ float g_bls_q[MQ * DIM];
__device__ float g_proj_s[MS * NSEQ * PP];
__device__ float g_proj_q[MQ * NSEQ * PP];
__device__ float g_cs_s[MS * PP * PP];
__device__ float g_cs_q[MQ * PP * PP];
__device__ float g_z_s[GS * DF];
__device__ float g_z_q[GQ * DF];
__device__ float g_mu_s[BB * DF];
__device__ float g_std_s[BB * DF];
__device__ float g_mu_q[BB * DF];
__device__ float g_std_q[BB * DF];
__device__ float g_gram[BB * 75 * 25];
// bf16 copies for tensor-core GEMMs
__device__ __nv_bfloat16 g_ab_s[MS * NSEQ * DIM];
__device__ __nv_bfloat16 g_ab_q[MQ * NSEQ * DIM];
__device__ __nv_bfloat16 g_wtb[DIM * DIM];        // w_bls^T: [n][k]
__device__ __nv_bfloat16 g_wp[2 * PP * DIM];      // cov_reducer^T hi/lo: [128][k]

// ---------------- helpers ----------------
__device__ __forceinline__ float tukey_f(float x) {
    float s = (x > 0.0f ? 1.0f : 0.0f) - (x < 0.0f ? 1.0f : 0.0f);
    return s * sqrtf(fabsf(x) + 1e-8f);
}

__device__ __forceinline__ float block_reduce_sum(float v, float* red, int tid) {
    red[tid] = v;
    __syncthreads();
    for (int s = 128; s > 0; s >>= 1) {
        if (tid < s) red[tid] += red[tid + s];
        __syncthreads();
    }
    float r = red[0];
    __syncthreads();
    return r;
}

__device__ __forceinline__ uint32_t smem_to_u32(const void* p) {
    uint32_t addr;
    asm("{ .reg .u64 tmp; cvta.to.shared.u64 tmp, %1; cvt.u32.u64 %0, tmp; }"
        : "=r"(addr) : "l"(p));
    return addr;
}

__device__ __forceinline__ void cp_async16(uint32_t dst, const void* src) {
    asm volatile("cp.async.cg.shared.global [%0], [%1], 16;" :: "r"(dst), "l"(src));
}
__device__ __forceinline__ void cp_commit() {
    asm volatile("cp.async.commit_group;" ::: "memory");
}
template <int N>
__device__ __forceinline__ void cp_wait() {
    asm volatile("cp.async.wait_group %0;" :: "n"(N) : "memory");
}

__device__ __forceinline__ void mma_bf16(float c[4], uint32_t a0, uint32_t a1,
                                         uint32_t a2, uint32_t a3,
                                         uint32_t b0, uint32_t b1) {
    asm volatile(
        "mma.sync.aligned.m16n8k16.row.col.f32.bf16.bf16.f32 "
        "{%0,%1,%2,%3}, {%4,%5,%6,%7}, {%8,%9}, {%0,%1,%2,%3};"
        : "+f"(c[0]), "+f"(c[1]), "+f"(c[2]), "+f"(c[3])
        : "r"(a0), "r"(a1), "r"(a2), "r"(a3), "r"(b0), "r"(b1));
}

__device__ __forceinline__ void ldsm_x4(uint32_t& r0, uint32_t& r1, uint32_t& r2,
                                        uint32_t& r3, uint32_t addr) {
    asm volatile("ldmatrix.sync.aligned.m8n8.x4.shared.b16 {%0,%1,%2,%3}, [%4];"
        : "=r"(r0), "=r"(r1), "=r"(r2), "=r"(r3) : "r"(addr));
}
__device__ __forceinline__ void ldsm_x2(uint32_t& r0, uint32_t& r1, uint32_t addr) {
    asm volatile("ldmatrix.sync.aligned.m8n8.x2.shared.b16 {%0,%1}, [%2];"
        : "=r"(r0), "=r"(r1) : "r"(addr));
}

// pack two fp32 into bf16x2 word: lo = first arg in low half
__device__ __forceinline__ uint32_t pack_bf16x2(float lo, float hi) {
    uint32_t r;
    asm("cvt.rn.bf16x2.f32 %0, %1, %2;" : "=r"(r) : "f"(hi), "f"(lo));
    return r;
}

// ---------------- 0a) fused convert fp32->bf16 + gap (streaming, 1 CTA/matrix) ----------------
__global__ void convert_gap_kernel(const float* __restrict__ feat,
                                   __nv_bfloat16* __restrict__ dst, int which) {
    float* gap = which ? g_gap_q : g_gap_s;
    int mi = blockIdx.x;
    int t = threadIdx.x;                      // 192 threads, 4 cols each
    const float4* src = (const float4*)(feat + (size_t)mi * NSEQ * DIM);
    __nv_bfloat16* o = dst + (size_t)mi * NSEQ * DIM;
    float s0 = 0.0f, s1 = 0.0f, s2 = 0.0f, s3 = 0.0f;
    #pragma unroll 2
    for (int n = 0; n < NSEQ; n++) {
        float4 v = src[n * 192 + t];
        s0 += v.x; s1 += v.y; s2 += v.z; s3 += v.w;
        uint2 pk;
        pk.x = pack_bf16x2(v.x, v.y);
        pk.y = pack_bf16x2(v.z, v.w);
        *(uint2*)(o + (size_t)n * DIM + 4 * t) = pk;
    }
    float* gp = gap + (size_t)mi * DIM + 4 * t;
    gp[0] = s0 * (1.0f / NSEQ);
    gp[1] = s1 * (1.0f / NSEQ);
    gp[2] = s2 * (1.0f / NSEQ);
    gp[3] = s3 * (1.0f / NSEQ);
}

// ---------------- 0b) transpose + convert w_bls -> g_wtb [n][k] bf16 ----------------
__global__ void convert_wt_kernel(const float* __restrict__ W) {
    __shared__ float t[32][33];
    int tx = threadIdx.x, ty = threadIdx.y;          // block 32x8
    int kbase = blockIdx.y * 32;
    int nbase = blockIdx.x * 32;
    #pragma unroll
    for (int j = 0; j < 32; j += 8)
        t[ty + j][tx] = W[(size_t)(kbase + ty + j) * DIM + nbase + tx];
    __syncthreads();
    #pragma unroll
    for (int j = 0; j < 32; j += 8)
        g_wtb[(size_t)(nbase + ty + j) * DIM + kbase + tx] =
            __float2bfloat16(t[tx][ty + j]);
}

// ---------------- 0c) transpose cov_reducer -> hi/lo bf16 [128][k] ----------------
__global__ void convert_wp_kernel(const float* __restrict__ R) {
    __shared__ float t[32][33];
    int tx = threadIdx.x, ty = threadIdx.y;          // block 32x8
    int kbase = blockIdx.y * 32;
    int nbase = blockIdx.x * 32;                     // blockIdx.x in {0,1}
    #pragma unroll
    for (int j = 0; j < 32; j += 8)
        t[ty + j][tx] = R[(size_t)(kbase + ty + j) * PP + nbase + tx];
    __syncthreads();
    #pragma unroll
    for (int j = 0; j < 32; j += 8) {
        int n = nbase + ty + j;
        int k = kbase + tx;
        float v = t[tx][ty + j];
        __nv_bfloat16 h = __float2bfloat16(v);
        float lo = v - __bfloat162float(h);
        g_wp[(size_t)n * DIM + k] = h;
        g_wp[(size_t)(PP + n) * DIM + k] = __float2bfloat16(lo);
    }
}

// ---------------- 2a) projection GEMM: bf16 mma + ldmatrix, W hi/lo, cp.async 2-stage ----------------
#define PROJ_SMEM_WORDS (2 * 6656 + 2 * 4096)
#define PROJ_SMEM_BYTES (PROJ_SMEM_WORDS * 4)

__global__ void __launch_bounds__(256, 2)
proj_bf16_kernel(const __nv_bfloat16* __restrict__ Abf,
                 const __nv_bfloat16* __restrict__ Wp, int which) {
    extern __shared__ uint32_t sh[];
    uint32_t* As = sh;                 // 2 x [208 rows x 32 words] (swizzled)
    uint32_t* Ws = sh + 13312;         // 2 x [128 rows x 32 words]
    uint32_t as_b = smem_to_u32(As);
    uint32_t ws_b = smem_to_u32(Ws);

    int mi = blockIdx.x;
    const __nv_bfloat16* A = Abf + (size_t)mi * NSEQ * DIM;

    int tid = threadIdx.x;
    int lane = tid & 31;
    int warp = tid >> 5;
    int wm = warp & 3;
    int wn = warp >> 2;
    int gid = lane >> 2;
    int tig = lane & 3;

    // ldmatrix per-lane bases
    int l15 = lane & 15;
    int halfA = lane >> 4;                  // k8-group select for A x4
    int swA = lane & 7;
    int l7 = lane & 7;
    int halfB = (lane >> 3) & 1;            // k8-group select for B x2
    uint32_t aLaneBase = as_b + l15 * 128;
    uint32_t bLaneBase = ws_b + (wn * 32 + l7) * 128;

    // zero-pad A rows 196..207 (both buffers)
    for (int i = tid; i < 768; i += 256) {
        int buf = i >= 384;
        As[buf * 6656 + 6272 + (i & 383)] = 0u;
    }

    auto issue = [&](int kc, int buf) {
        for (int idx = tid; idx < 1568; idx += 256) {
            int row = idx >> 3;
            int q = idx & 7;
            uint32_t dst = as_b + (buf * 6656 + row * 32 + ((q ^ (row & 7)) << 2)) * 4;
            cp_async16(dst, A + (size_t)row * DIM + kc * 64 + q * 8);
        }
        for (int idx = tid; idx < 1024; idx += 256) {
            int r = idx >> 3;                 // 0..127 (hi rows 0-63, lo rows 64-127)
            int q = idx & 7;
            uint32_t dst = ws_b + (buf * 4096 + r * 32 + ((q ^ (r & 7)) << 2)) * 4;
            cp_async16(dst, Wp + (size_t)r * DIM + kc * 64 + q * 8);
        }
        cp_commit();
    };

    float acc[4][4][4];
    #pragma unroll
    for (int mt = 0; mt < 4; mt++)
        #pragma unroll
        for (int nf = 0; nf < 4; nf++)
            #pragma unroll
            for (int c = 0; c < 4; c++) acc[mt][nf][c] = 0.0f;

    issue(0, 0);
    for (int kc = 0; kc < 12; kc++) {
        int buf = kc & 1;
        if (kc < 11) { issue(kc + 1, buf ^ 1); cp_wait<1>(); }
        else cp_wait<0>();
        __syncthreads();
        uint32_t aBuf = aLaneBase + buf * 26624;
        uint32_t bBuf = bLaneBase + buf * 16384;

        #pragma unroll
        for (int ks = 0; ks < 4; ks++) {
            int gB = 2 * ks + halfB;
            uint32_t bOff = (uint32_t)((gB ^ l7) << 4);
            uint32_t bh0[4], bh1[4], bl0[4], bl1[4];
            #pragma unroll
            for (int nf = 0; nf < 4; nf++) {
                ldsm_x2(bh0[nf], bh1[nf], bBuf + nf * 1024 + bOff);
                ldsm_x2(bl0[nf], bl1[nf], bBuf + 8192 + nf * 1024 + bOff);
            }
            int gA = 2 * ks + halfA;
            uint32_t aOff = (uint32_t)((gA ^ swA) << 4);
            #pragma unroll
            for (int mt = 0; mt < 4; mt++) {
                int mtg = wm + 4 * mt;
                if (mtg < 13) {
                    uint32_t a0, a1, a2, a3;
                    ldsm_x4(a0, a1, a2, a3, aBuf + mtg * 2048 + aOff);
                    #pragma unroll
                    for (int nf = 0; nf < 4; nf++) {
                        mma_bf16(acc[mt][nf], a0, a1, a2, a3, bh0[nf], bh1[nf]);
                        mma_bf16(acc[mt][nf], a0, a1, a2, a3, bl0[nf], bl1[nf]);
                    }
                }
            }
        }
        __syncthreads();
    }

    // epilogue: direct fp32 writes
    float* outp = (which ? g_proj_q : g_proj_s) + (size_t)mi * NSEQ * PP;
    #pragma unroll
    for (int nf = 0; nf < 4; nf++) {
        int cb = wn * 32 + nf * 8 + 2 * tig;
        #pragma unroll
        for (int mt = 0; mt < 4; mt++) {
            int mtg = wm + 4 * mt;
            if (mtg < 13) {
                int r0 = mtg * 16 + gid;
                int r1 = r0 + 8;
                if (r0 < NSEQ) {
                    outp[(size_t)r0 * PP + cb] = acc[mt][nf][0];
                    outp[(size_t)r0 * PP + cb + 1] = acc[mt][nf][1];
                }
                if (r1 < NSEQ) {
                    outp[(size_t)r1 * PP + cb] = acc[mt][nf][2];
                    outp[(size_t)r1 * PP + cb + 1] = acc[mt][nf][3];
                }
            }
        }
    }
}

// ---------------- 2b) BLS GEMM: bf16 mma + ldmatrix, cp.async 2-stage ----------------
#define BLS_SMEM_WORDS (2 * 6656 + 2 * 2048 + 256)
#define BLS_SMEM_BYTES (BLS_SMEM_WORDS * 4)

__global__ void __launch_bounds__(256, 2)
bls_bf16_kernel(const __nv_bfloat16* __restrict__ Abf,
                const __nv_bfloat16* __restrict__ Wt,
                const float* __restrict__ bias, int which) {
    extern __shared__ uint32_t sh[];
    uint32_t* As = sh;                 // 2 x [208 x 32]
    uint32_t* Ws = sh + 13312;         // 2 x [64 x 32]
    float (*colsum)[64] = (float(*)[64])(sh + 13312 + 4096);
    uint32_t as_b = smem_to_u32(As);
    uint32_t ws_b = smem_to_u32(Ws);

    int nt = blockIdx.x;
    int mi = blockIdx.y;
    int n0 = nt * 64;
    const __nv_bfloat16* A = Abf + (size_t)mi * NSEQ * DIM;

    int tid = threadIdx.x;
    int lane = tid & 31;
    int warp = tid >> 5;
    int wm = warp & 3;
    int wn = warp >> 2;
    int gid = lane >> 2;
    int tig = lane & 3;

    int l15 = lane & 15;
    int halfA = lane >> 4;
    int swA = lane & 7;
    int l7 = lane & 7;
    int halfB = (lane >> 3) & 1;
    uint32_t aLaneBase = as_b + l15 * 128;
    uint32_t bLaneBase = ws_b + (wn * 32 + l7) * 128;

    for (int i = tid; i < 768; i += 256) {
        int buf = i >= 384;
        As[buf * 6656 + 6272 + (i & 383)] = 0u;
    }

    auto issue = [&](int kc, int buf) {
        for (int idx = tid; idx < 1568; idx += 256) {
            int row = idx >> 3;
            int q = idx & 7;
            uint32_t dst = as_b + (buf * 6656 + row * 32 + ((q ^ (row & 7)) << 2)) * 4;
            cp_async16(dst, A + (size_t)row * DIM + kc * 64 + q * 8);
        }
        for (int idx = tid; idx < 512; idx += 256) {
            int r = idx >> 3;
            int q = idx & 7;
            uint32_t dst = ws_b + (buf * 2048 + r * 32 + ((q ^ (r & 7)) << 2)) * 4;
            cp_async16(dst, Wt + (size_t)(n0 + r) * DIM + kc * 64 + q * 8);
        }
        cp_commit();
    };

    float acc[4][4][4];
    #pragma unroll
    for (int mt = 0; mt < 4; mt++)
        #pragma unroll
        for (int nf = 0; nf < 4; nf++)
            #pragma unroll
            for (int c = 0; c < 4; c++) acc[mt][nf][c] = 0.0f;

    issue(0, 0);
    for (int kc = 0; kc < 12; kc++) {
        int buf = kc & 1;
        if (kc < 11) { issue(kc + 1, buf ^ 1); cp_wait<1>(); }
        else cp_wait<0>();
        __syncthreads();
        uint32_t aBuf = aLaneBase + buf * 26624;
        uint32_t bBuf = bLaneBase + buf * 8192;

        #pragma unroll
        for (int ks = 0; ks < 4; ks++) {
            int gB = 2 * ks + halfB;
            uint32_t bOff = (uint32_t)((gB ^ l7) << 4);
            uint32_t b0[4], b1[4];
            #pragma unroll
            for (int nf = 0; nf < 4; nf++)
                ldsm_x2(b0[nf], b1[nf], bBuf + nf * 1024 + bOff);
            int gA = 2 * ks + halfA;
            uint32_t aOff = (uint32_t)((gA ^ swA) << 4);
            #pragma unroll
            for (int mt = 0; mt < 4; mt++) {
                int mtg = wm + 4 * mt;
                if (mtg < 13) {
                    uint32_t a0, a1, a2, a3;
                    ldsm_x4(a0, a1, a2, a3, aBuf + mtg * 2048 + aOff);
                    #pragma unroll
                    for (int nf = 0; nf < 4; nf++)
                        mma_bf16(acc[mt][nf], a0, a1, a2, a3, b0[nf], b1[nf]);
                }
            }
        }
        __syncthreads();
    }

    // epilogue: tanh(acc + bias) column-mean over valid rows
    #pragma unroll
    for (int nf = 0; nf < 4; nf++) {
        int cb = n0 + wn * 32 + nf * 8 + 2 * tig;
        float bv0 = bias[cb];
        float bv1 = bias[cb + 1];
        float p0 = 0.0f, p1 = 0.0f;
        #pragma unroll
        for (int mt = 0; mt < 4; mt++) {
            int mtg = wm + 4 * mt;
            if (mtg < 13) {
                int r0 = mtg * 16 + gid;
                int r1 = r0 + 8;
                if (r0 < NSEQ) {
                    p0 += tanhf(acc[mt][nf][0] + bv0);
                    p1 += tanhf(acc[mt][nf][1] + bv1);
                }
                if (r1 < NSEQ) {
                    p0 += tanhf(acc[mt][nf][2] + bv0);
                    p1 += tanhf(acc[mt][nf][3] + bv1);
                }
            }
        }
        #pragma unroll
        for (int off = 4; off <= 16; off <<= 1) {
            p0 += __shfl_xor_sync(0xffffffff, p0, off);
            p1 += __shfl_xor_sync(0xffffffff, p1, off);
        }
        if (gid == 0) {
            colsum[wm][wn * 32 + nf * 8 + 2 * tig]     = p0;
            colsum[wm][wn * 32 + nf * 8 + 2 * tig + 1] = p1;
        }
    }
    __syncthreads();
    if (tid < 64) {
        float s = colsum[0][tid] + colsum[1][tid] + colsum[2][tid] + colsum[3][tid];
        float* outp = which ? g_bls_q : g_bls_s;
        outp[(size_t)mi * DIM + n0 + tid] = s * (1.0f / NSEQ);
    }
}

// ---------------- 3) cov + Newton-Schulz matrix sqrt ----------------
#define CS_SMEM_FLOATS (NSEQ * 65 + 3 * 64 * 65 + 256 + 64)

__global__ void covsqrt_kernel(int which) {
    extern __shared__ float fsh[];
    float* X = fsh;
    float* Yb = X + NSEQ * 65;
    float* Zb = Yb + 64 * 65;
    float* Tb = Zb + 64 * 65;
    float* red = Tb + 64 * 65;
    float* mean = red + 256;

    const float* proj = which ? g_proj_q : g_proj_s;
    float* cs = which ? g_cs_q : g_cs_s;
    int mi = blockIdx.x;
    int tx = threadIdx.x, ty = threadIdx.y;
    int tid = ty * 16 + tx;

    for (int idx = tid; idx < NSEQ * PP; idx += 256) {
        int n = idx >> 6;
        int p = idx & 63;
        X[n * 65 + p] = proj[(size_t)mi * NSEQ * PP + idx];
    }
    __syncthreads();
    if (tid < 64) {
        float s = 0.0f;
        for (int n = 0; n < NSEQ; n++) s += X[n * 65 + tid];
        mean[tid] = s * (1.0f / NSEQ);
    }
    __syncthreads();
    for (int idx = tid; idx < NSEQ * PP; idx += 256) {
        int n = idx >> 6;
        int p = idx & 63;
        X[n * 65 + p] -= mean[p];
    }
    __syncthreads();

    float cacc[4][4];
    #pragma unroll
    for (int i = 0; i < 4; i++)
        #pragma unroll
        for (int j = 0; j < 4; j++) cacc[i][j] = 0.0f;
    for (int n = 0; n < NSEQ; n++) {
        float a[4], b[4];
        #pragma unroll
        for (int i = 0; i < 4; i++) a[i] = X[n * 65 + ty + 16 * i];
        #pragma unroll
        for (int j = 0; j < 4; j++) b[j] = X[n * 65 + tx + 16 * j];
        #pragma unroll
        for (int i = 0; i < 4; i++)
            #pragma unroll
            for (int j = 0; j < 4; j++) cacc[i][j] += a[i] * b[j];
    }
    float ss = 0.0f;
    #pragma unroll
    for (int i = 0; i < 4; i++) {
        int p = ty + 16 * i;
        #pragma unroll
        for (int j = 0; j < 4; j++) {
            int q = tx + 16 * j;
            float v = cacc[i][j] * (1.0f / 195.0f) + ((p == q) ? 1e-5f : 0.0f);
            Yb[p * 65 + q] = v;
            ss += v * v;
        }
    }
    float total = block_reduce_sum(ss, red, tid);
    float norm = sqrtf(total);
    float inv = 1.0f / (norm + 1e-8f);
    #pragma unroll
    for (int i = 0; i < 4; i++) {
        int p = ty + 16 * i;
        #pragma unroll
        for (int j = 0; j < 4; j++) {
            int q = tx + 16 * j;
            Yb[p * 65 + q] *= inv;
            Zb[p * 65 + q] = (p == q) ? 1.0f : 0.0f;
        }
    }
    __syncthreads();

    for (int it = 0; it < 3; it++) {
        float tacc[4][4];
        #pragma unroll
        for (int i = 0; i < 4; i++)
            #pragma unroll
            for (int j = 0; j < 4; j++) tacc[i][j] = 0.0f;
        for (int k = 0; k < 64; k++) {
            float a[4], b[4];
            #pragma unroll
            for (int i = 0; i < 4; i++) a[i] = Zb[(ty + 16 * i) * 65 + k];
            #pragma unroll
            for (int j = 0; j < 4; j++) b[j] = Yb[k * 65 + tx + 16 * j];
            #pragma unroll
            for (int i = 0; i < 4; i++)
                #pragma unroll
                for (int j = 0; j < 4; j++) tacc[i][j] += a[i] * b[j];
        }
        #pragma unroll
        for (int i = 0; i < 4; i++) {
            int p = ty + 16 * i;
            #pragma unroll
            for (int j = 0; j < 4; j++) {
                int q = tx + 16 * j;
                Tb[p * 65 + q] = ((p == q) ? 1.5f : 0.0f) - 0.5f * tacc[i][j];
            }
        }
        __syncthreads();
        float yacc[4][4], zacc[4][4];
        #pragma unroll
        for (int i = 0; i < 4; i++)
            #pragma unroll
            for (int j = 0; j < 4; j++) { yacc[i][j] = 0.0f; zacc[i][j] = 0.0f; }
        for (int k = 0; k < 64; k++) {
            float ya[4], tb[4], ta[4], zb2[4];
            #pragma unroll
            for (int i = 0; i < 4; i++) {
                ya[i] = Yb[(ty + 16 * i) * 65 + k];
                ta[i] = Tb[(ty + 16 * i) * 65 + k];
            }
            #pragma unroll
            for (int j = 0; j < 4; j++) {
                tb[j] = Tb[k * 65 + tx + 16 * j];
                zb2[j] = Zb[k * 65 + tx + 16 * j];
            }
            #pragma unroll
            for (int i = 0; i < 4; i++)
                #pragma unroll
                for (int j = 0; j < 4; j++) {
                    yacc[i][j] += ya[i] * tb[j];
                    zacc[i][j] += ta[i] * zb2[j];
                }
        }
        __syncthreads();
        #pragma unroll
        for (int i = 0; i < 4; i++) {
            int p = ty + 16 * i;
            #pragma unroll
            for (int j = 0; j < 4; j++) {
                int q = tx + 16 * j;
                Yb[p * 65 + q] = yacc[i][j];
                Zb[p * 65 + q] = zacc[i][j];
            }
        }
        __syncthreads();
    }

    float sc = sqrtf(norm + 1e-8f);
    #pragma unroll
    for (int i = 0; i < 4; i++) {
        int p = ty + 16 * i;
        #pragma unroll
        for (int j = 0; j < 4; j++) {
            int q = tx + 16 * j;
            cs[(size_t)mi * 4096 + p * 64 + q] = Yb[p * 65 + q] * sc;
        }
    }
}

// ---------------- 4) fuse ----------------
__global__ void fuse_kernel(int which) {
    const float* gap = which ? g_gap_q : g_gap_s;
    const float* cs = which ? g_cs_q : g_cs_s;
    const float* bls = which ? g_bls_q : g_bls_s;
    float* z = which ? g_z_q : g_z_s;
    int Mt = which ? MTQ : MTS;

    __shared__ float buf[DF];
    __shared__ float red[256];
    int g = blockIdx.x;
    int tid = threadIdx.x;
    int m0 = g * NV;

    float ss0 = 0.0f, ss1 = 0.0f, ss2 = 0.0f;

    for (int j = tid; j < SEC0; j += 256) {
        int l = j / DIM;
        int f = j - l * DIM;
        const float* src = gap + ((size_t)(l * Mt + m0)) * DIM + f;
        float v = 0.0f;
        #pragma unroll
        for (int vi = 0; vi < NV; vi++) v += src[(size_t)vi * DIM];
        v *= (1.0f / NV);
        float t = tukey_f(v);
        buf[j] = t;
        ss0 += t * t;
    }
    for (int j = tid; j < SEC1; j += 256) {
        int l = j / TRI;
        int f = j - l * TRI;
        int i = 0, rem = f;
        while (rem >= 64 - i) { rem -= 64 - i; i++; }
        int jj = i + rem;
        const float* src = cs + ((size_t)(l * Mt + m0)) * 4096 + i * 64 + jj;
        float v = 0.0f;
        #pragma unroll
        for (int vi = 0; vi < NV; vi++) v += src[(size_t)vi * 4096];
        v *= (1.0f / NV);
        float t = tukey_f(v);
        buf[SEC0 + j] = t;
        ss1 += t * t;
    }
    for (int j = tid; j < SEC0; j += 256) {
        int l = j / DIM;
        int f = j - l * DIM;
        const float* src = bls + ((size_t)(l * Mt + m0)) * DIM + f;
        float v = 0.0f;
        #pragma unroll
        for (int vi = 0; vi < NV; vi++) v += src[(size_t)vi * DIM];
        v *= (1.0f / NV);
        float t = tukey_f(v);
        buf[SEC0 + SEC1 + j] = t;
        ss2 += t * t;
    }
    __syncthreads();
    float S0 = block_reduce_sum(ss0, red, tid);
    float S1 = block_reduce_sum(ss1, red, tid);
    float S2 = block_reduce_sum(ss2, red, tid);
    float inv0 = 1.0f / fmaxf(sqrtf(S0), 1e-12f) * 1.0f;
    float inv1 = 1.0f / fmaxf(sqrtf(S1), 1e-12f) * 0.8f;
    float inv2 = 1.0f / fmaxf(sqrtf(S2), 1e-12f) * 0.1f;

    for (int j = tid; j < DF; j += 256) {
        float w = (j < SEC0) ? inv0 : (j < SEC0 + SEC1) ? inv1 : inv2;
        z[(size_t)g * DF + j] = buf[j] * w;
    }
}

// ---------------- 5) per-(b,feature) stats ----------------
__global__ void stats_kernel() {
    int idx = blockIdx.x * 256 + threadIdx.x;
    if (idx >= BB * DF) return;
    int b = idx / DF;
    int f = idx - b * DF;
    {
        const float* zs = g_z_s + (size_t)b * NSUP * DF + f;
        float m = 0.0f;
        for (int s = 0; s < NSUP; s++) m += zs[(size_t)s * DF];
        m *= (1.0f / NSUP);
        float v = 0.0f;
        for (int s = 0; s < NSUP; s++) { float d = zs[(size_t)s * DF] - m; v += d * d; }
        v *= (1.0f / (NSUP - 1));
        g_mu_s[idx] = m;
        g_std_s[idx] = sqrtf(v) + 1e-8f;
    }
    {
        const float* zq = g_z_q + (size_t)b * NQRY * DF + f;
        float m = 0.0f;
        for (int s = 0; s < NQRY; s++) m += zq[(size_t)s * DF];
        m *= (1.0f / NQRY);
        float v = 0.0f;
        for (int s = 0; s < NQRY; s++) { float d = zq[(size_t)s * DF] - m; v += d * d; }
        v *= (1.0f / (NQRY - 1));
        g_mu_q[idx] = m;
        g_std_q[idx] = sqrtf(v) + 1e-8f;
    }
}

// ---------------- 6) center/standardize + row l2norm ----------------
__global__ void rownorm_kernel(int which) {
    __shared__ float red[256];
    int g = blockIdx.x;
    int tid = threadIdx.x;
    if (which == 0) {
        int b = g / NSUP;
        float* z = g_z_s + (size_t)g * DF;
        const float* mu = g_mu_s + (size_t)b * DF;
        float ss = 0.0f;
        for (int f = tid; f < DF; f += 256) { float v = z[f] - mu[f]; ss += v * v; }
        float S = block_reduce_sum(ss, red, tid);
        float inv = 1.0f / fmaxf(sqrtf(S), 1e-12f);
        for (int f = tid; f < DF; f += 256) z[f] = (z[f] - mu[f]) * inv;
    } else {
        int b = g / NQRY;
        float* z = g_z_q + (size_t)g * DF;
        const float* muq = g_mu_q + (size_t)b * DF;
        const float* sdq = g_std_q + (size_t)b * DF;
        const float* sds = g_std_s + (size_t)b * DF;
        float ss = 0.0f;
        for (int f = tid; f < DF; f += 256) {
            float v = (z[f] - muq[f]) / sdq[f] * sds[f];
            ss += v * v;
        }
        float S = block_reduce_sum(ss, red, tid);
        float inv = 1.0f / fmaxf(sqrtf(S), 1e-12f);
        for (int f = tid; f < DF; f += 256) {
            float v = (z[f] - muq[f]) / sdq[f] * sds[f];
            z[f] = v * inv;
        }
    }
}

// ---------------- 7) gram ----------------
__global__ void gram_kernel() {
    int b = blockIdx.x;
    int i = blockIdx.y;
    int tid = threadIdx.x;
    const float* rowi = (i < NSUP)
        ? g_z_s + (size_t)(b * NSUP + i) * DF
        : g_z_q + (size_t)(b * NQRY + (i - NSUP)) * DF;
    const float* zsb = g_z_s + (size_t)b * NSUP * DF;

    float part[NSUP];
    #pragma unroll
    for (int j = 0; j < NSUP; j++) part[j] = 0.0f;
    for (int f = tid; f < DF; f += 256) {
        float a = rowi[f];
        #pragma unroll
        for (int j = 0; j < NSUP; j++) part[j] += a * zsb[(size_t)j * DF + f];
    }
    __shared__ float red[256];
    for (int j = 0; j < NSUP; j++) {
        red[tid] = part[j];
        __syncthreads();
        for (int s = 128; s > 0; s >>= 1) {
            if (tid < s) red[tid] += red[tid + s];
            __syncthreads();
        }
        if (tid == 0) g_gram[(b * 75 + i) * 25 + j] = red[0];
        __syncthreads();
    }
}

// ---------------- 8) ridge solve + output ----------------
__global__ void solve_kernel(const int* __restrict__ y_sup, float* __restrict__ out) {
    int b = blockIdx.x;
    int tid = threadIdx.x;
    __shared__ float Ab[25][31];
    __shared__ float alpha[25][5];
    const float lam = 0.1f * ((float)DF / 500.0f);

    for (int idx = tid; idx < 25 * 30; idx += 32) {
        int i = idx / 30;
        int j = idx - i * 30;
        if (j < 25) {
            Ab[i][j] = g_gram[(b * 75 + i) * 25 + j] + ((i == j) ? lam : 0.0f);
        } else {
            int c = j - 25;
            Ab[i][j] = (y_sup[b * NSUP + i] == c) ? 1.0f : 0.0f;
        }
    }
    __syncthreads();
    for (int k = 0; k < 25; k++) {
        if (tid < 25 && tid != k) {
            float factor = Ab[tid][k] / Ab[k][k];
            for (int j = k; j < 30; j++) Ab[tid][j] -= factor * Ab[k][j];
        }
        __syncthreads();
    }
    for (int idx = tid; idx < 125; idx += 32) {
        int i = idx / 5;
        int c = idx - i * 5;
        alpha[i][c] = Ab[i][25 + c] / Ab[i][i];
    }
    __syncthreads();
    for (int idx = tid; idx < NQRY * NC; idx += 32) {
        int q = idx / NC;
        int c = idx - q * NC;
        float s = 0.0f;
        #pragma unroll
        for (int j = 0; j < 25; j++) s += g_gram[(b * 75 + 25 + q) * 25 + j] * alpha[j][c];
        out[((size_t)b * NQRY + q) * NC + c] = 20.0f * s;
    }
}

// ---------------- launch ----------------
extern "C" void kernel_launch(void* const* d_in, const int* in_sizes, int n_in,
                              void* d_out, int out_size) {
    const float* feats_sup   = (const float*)d_in[0];
    const float* feats_qry   = (const float*)d_in[1];
    const float* cov_reducer = (const float*)d_in[2];
    const float* w_bls       = (const float*)d_in[3];
    const float* b_bls       = (const float*)d_in[4];
    const int*   y_sup       = (const int*)d_in[5];
    float* out = (float*)d_out;

    static const size_t CS_SMEM = (size_t)CS_SMEM_FLOATS * sizeof(float);
    cudaFuncSetAttribute(covsqrt_kernel, cudaFuncAttributeMaxDynamicSharedMemorySize, (int)CS_SMEM);
    cudaFuncSetAttribute(bls_bf16_kernel, cudaFuncAttributeMaxDynamicSharedMemorySize, BLS_SMEM_BYTES);
    cudaFuncSetAttribute(proj_bf16_kernel, cudaFuncAttributeMaxDynamicSharedMemorySize, PROJ_SMEM_BYTES);

    dim3 blk2d(16, 16);

    __nv_bfloat16 *ab_s, *ab_q, *wtb, *wp;
    cudaGetSymbolAddress((void**)&ab_s, g_ab_s);
    cudaGetSymbolAddress((void**)&ab_q, g_ab_q);
    cudaGetSymbolAddress((void**)&wtb, g_wtb);
    cudaGetSymbolAddress((void**)&wp, g_wp);

    // fused streaming bf16 convert + gap
    convert_gap_kernel<<<MS, 192>>>(feats_sup, ab_s, 0);
    convert_gap_kernel<<<MQ, 192>>>(feats_qry, ab_q, 1);
    convert_wt_kernel<<<dim3(24, 24), dim3(32, 8)>>>(w_bls);
    convert_wp_kernel<<<dim3(2, 24), dim3(32, 8)>>>(cov_reducer);

    // projection GEMM (bf16 tensor cores, W hi/lo split, ldmatrix)
    proj_bf16_kernel<<<MS, 256, PROJ_SMEM_BYTES>>>(ab_s, wp, 0);
    proj_bf16_kernel<<<MQ, 256, PROJ_SMEM_BYTES>>>(ab_q, wp, 1);

    // BLS GEMM (bf16 tensor cores, cp.async + ldmatrix)
    bls_bf16_kernel<<<dim3(12, MS), 256, BLS_SMEM_BYTES>>>(ab_s, wtb, b_bls, 0);
    bls_bf16_kernel<<<dim3(12, MQ), 256, BLS_SMEM_BYTES>>>(ab_q, wtb, b_bls, 1);

    // cov + Newton-Schulz sqrt
    covsqrt_kernel<<<MS, blk2d, CS_SMEM>>>(0);
    covsqrt_kernel<<<MQ, blk2d, CS_SMEM>>>(1);

    // fuse
    fuse_kernel<<<GS, 256>>>(0);
    fuse_kernel<<<GQ, 256>>>(1);

    // stats
    stats_kernel<<<(BB * DF + 255) / 256, 256>>>();

    // center + l2norm rows
    rownorm_kernel<<<GS, 256>>>(0);
    rownorm_kernel<<<GQ, 256>>>(1);

    // gram
    gram_kernel<<<dim3(BB, 75), 256>>>();

    // solve + logits
    solve_kernel<<<BB, 32>>>(y_sup, out);
}

// round 17
// speedup vs baseline: 6.4026x; 1.0096x over previous
#include <cuda_runtime.h>
#include <cuda_bf16.h>
#include <math.h>
#include <stdint.h>

// ---------------- problem constants ----------------
#define LN    2
#define NSEQ  196
#define DIM   768
#define PP    64
#define BB    2
#define NSUP  25
#define NQRY  50
#define NV    5
#define MS    500
#define MQ    1000
#define MTS   250
#define MTQ   500
#define GS    50
#define GQ    100
#define TRI   2080
#define SEC0  1536
#define SEC1  4160
#define DF    7232
#define NC    5

// ---------------- scratch ----------------
__device__ float g_gap_s[MS * DIM];
__device__ float g_gap_q[MQ * DIM];
__device__ float g_bls_s[MS * DIM];
__device__ float g_bls_q[MQ * DIM];
__device__ float g_proj_s[MS * NSEQ * PP];
__device__ float g_proj_q[MQ * NSEQ * PP];
__device__ float g_cs_s[MS * PP * PP];
__device__ float g_cs_q[MQ * PP * PP];
__device__ float g_z_s[GS * DF];
__device__ float g_z_q[GQ * DF];
__device__ float g_mu_s[BB * DF];
__device__ float g_std_s[BB * DF];
__device__ float g_mu_q[BB * DF];
__device__ float g_std_q[BB * DF];
__device__ float g_gram[BB * 75 * 25];
// bf16 copies for tensor-core GEMMs
__device__ __nv_bfloat16 g_ab_s[MS * NSEQ * DIM];
__device__ __nv_bfloat16 g_ab_q[MQ * NSEQ * DIM];
__device__ __nv_bfloat16 g_wtb[DIM * DIM];        // w_bls^T: [n][k]
__device__ __nv_bfloat16 g_wp[2 * PP * DIM];      // cov_reducer^T hi/lo: [128][k]

// ---------------- helpers ----------------
__device__ __forceinline__ float tukey_f(float x) {
    float s = (x > 0.0f ? 1.0f : 0.0f) - (x < 0.0f ? 1.0f : 0.0f);
    return s * sqrtf(fabsf(x) + 1e-8f);
}

__device__ __forceinline__ float block_reduce_sum(float v, float* red, int tid) {
    red[tid] = v;
    __syncthreads();
    for (int s = 128; s > 0; s >>= 1) {
        if (tid < s) red[tid] += red[tid + s];
        __syncthreads();
    }
    float r = red[0];
    __syncthreads();
    return r;
}

__device__ __forceinline__ uint32_t smem_to_u32(const void* p) {
    uint32_t addr;
    asm("{ .reg .u64 tmp; cvta.to.shared.u64 tmp, %1; cvt.u32.u64 %0, tmp; }"
        : "=r"(addr) : "l"(p));
    return addr;
}

__device__ __forceinline__ void cp_async16(uint32_t dst, const void* src) {
    asm volatile("cp.async.cg.shared.global [%0], [%1], 16;" :: "r"(dst), "l"(src));
}
__device__ __forceinline__ void cp_commit() {
    asm volatile("cp.async.commit_group;" ::: "memory");
}
template <int N>
__device__ __forceinline__ void cp_wait() {
    asm volatile("cp.async.wait_group %0;" :: "n"(N) : "memory");
}

__device__ __forceinline__ void mma_bf16(float c[4], uint32_t a0, uint32_t a1,
                                         uint32_t a2, uint32_t a3,
                                         uint32_t b0, uint32_t b1) {
    asm volatile(
        "mma.sync.aligned.m16n8k16.row.col.f32.bf16.bf16.f32 "
        "{%0,%1,%2,%3}, {%4,%5,%6,%7}, {%8,%9}, {%0,%1,%2,%3};"
        : "+f"(c[0]), "+f"(c[1]), "+f"(c[2]), "+f"(c[3])
        : "r"(a0), "r"(a1), "r"(a2), "r"(a3), "r"(b0), "r"(b1));
}

__device__ __forceinline__ void ldsm_x4(uint32_t& r0, uint32_t& r1, uint32_t& r2,
                                        uint32_t& r3, uint32_t addr) {
    asm volatile("ldmatrix.sync.aligned.m8n8.x4.shared.b16 {%0,%1,%2,%3}, [%4];"
        : "=r"(r0), "=r"(r1), "=r"(r2), "=r"(r3) : "r"(addr));
}
__device__ __forceinline__ void ldsm_x2(uint32_t& r0, uint32_t& r1, uint32_t addr) {
    asm volatile("ldmatrix.sync.aligned.m8n8.x2.shared.b16 {%0,%1}, [%2];"
        : "=r"(r0), "=r"(r1) : "r"(addr));
}

// pack two fp32 into bf16x2 word: lo = first arg in low half
__device__ __forceinline__ uint32_t pack_bf16x2(float lo, float hi) {
    uint32_t r;
    asm("cvt.rn.bf16x2.f32 %0, %1, %2;" : "=r"(r) : "f"(hi), "f"(lo));
    return r;
}

// ---------------- 0a) fused convert fp32->bf16 + gap (both sets, 1 CTA/matrix) ----------------
__global__ void convert_gap_kernel(const float* __restrict__ fs,
                                   const float* __restrict__ fq,
                                   __nv_bfloat16* __restrict__ ds,
                                   __nv_bfloat16* __restrict__ dq) {
    int gmi = blockIdx.x;
    int which = gmi >= MS;
    int mi = which ? gmi - MS : gmi;
    const float* feat = which ? fq : fs;
    __nv_bfloat16* dst = which ? dq : ds;
    float* gap = which ? g_gap_q : g_gap_s;

    int t = threadIdx.x;                      // 192 threads, 4 cols each
    const float4* src = (const float4*)(feat + (size_t)mi * NSEQ * DIM);
    __nv_bfloat16* o = dst + (size_t)mi * NSEQ * DIM;
    float s0 = 0.0f, s1 = 0.0f, s2 = 0.0f, s3 = 0.0f;
    #pragma unroll 2
    for (int n = 0; n < NSEQ; n++) {
        float4 v = src[n * 192 + t];
        s0 += v.x; s1 += v.y; s2 += v.z; s3 += v.w;
        uint2 pk;
        pk.x = pack_bf16x2(v.x, v.y);
        pk.y = pack_bf16x2(v.z, v.w);
        *(uint2*)(o + (size_t)n * DIM + 4 * t) = pk;
    }
    float* gp = gap + (size_t)mi * DIM + 4 * t;
    gp[0] = s0 * (1.0f / NSEQ);
    gp[1] = s1 * (1.0f / NSEQ);
    gp[2] = s2 * (1.0f / NSEQ);
    gp[3] = s3 * (1.0f / NSEQ);
}

// ---------------- 0b) transpose + convert w_bls -> g_wtb [n][k] bf16 ----------------
__global__ void convert_wt_kernel(const float* __restrict__ W) {
    __shared__ float t[32][33];
    int tx = threadIdx.x, ty = threadIdx.y;          // block 32x8
    int kbase = blockIdx.y * 32;
    int nbase = blockIdx.x * 32;
    #pragma unroll
    for (int j = 0; j < 32; j += 8)
        t[ty + j][tx] = W[(size_t)(kbase + ty + j) * DIM + nbase + tx];
    __syncthreads();
    #pragma unroll
    for (int j = 0; j < 32; j += 8)
        g_wtb[(size_t)(nbase + ty + j) * DIM + kbase + tx] =
            __float2bfloat16(t[tx][ty + j]);
}

// ---------------- 0c) transpose cov_reducer -> hi/lo bf16 [128][k] ----------------
__global__ void convert_wp_kernel(const float* __restrict__ R) {
    __shared__ float t[32][33];
    int tx = threadIdx.x, ty = threadIdx.y;          // block 32x8
    int kbase = blockIdx.y * 32;
    int nbase = blockIdx.x * 32;                     // blockIdx.x in {0,1}
    #pragma unroll
    for (int j = 0; j < 32; j += 8)
        t[ty + j][tx] = R[(size_t)(kbase + ty + j) * PP + nbase + tx];
    __syncthreads();
    #pragma unroll
    for (int j = 0; j < 32; j += 8) {
        int n = nbase + ty + j;
        int k = kbase + tx;
        float v = t[tx][ty + j];
        __nv_bfloat16 h = __float2bfloat16(v);
        float lo = v - __bfloat162float(h);
        g_wp[(size_t)n * DIM + k] = h;
        g_wp[(size_t)(PP + n) * DIM + k] = __float2bfloat16(lo);
    }
}

// ---------------- 2a) projection GEMM: bf16 mma + ldmatrix, W hi/lo, cp.async 2-stage ----------------
#define PROJ_SMEM_WORDS (2 * 6656 + 2 * 4096)
#define PROJ_SMEM_BYTES (PROJ_SMEM_WORDS * 4)

__global__ void __launch_bounds__(256, 2)
proj_bf16_kernel(const __nv_bfloat16* __restrict__ Abf,
                 const __nv_bfloat16* __restrict__ Wp, int which) {
    extern __shared__ uint32_t sh[];
    uint32_t* As = sh;                 // 2 x [208 rows x 32 words] (swizzled)
    uint32_t* Ws = sh + 13312;         // 2 x [128 rows x 32 words]
    uint32_t as_b = smem_to_u32(As);
    uint32_t ws_b = smem_to_u32(Ws);

    int mi = blockIdx.x;
    const __nv_bfloat16* A = Abf + (size_t)mi * NSEQ * DIM;

    int tid = threadIdx.x;
    int lane = tid & 31;
    int warp = tid >> 5;
    int wm = warp & 3;
    int wn = warp >> 2;
    int gid = lane >> 2;
    int tig = lane & 3;

    int l15 = lane & 15;
    int halfA = lane >> 4;
    int swA = lane & 7;
    int l7 = lane & 7;
    int halfB = (lane >> 3) & 1;
    uint32_t aLaneBase = as_b + l15 * 128;
    uint32_t bLaneBase = ws_b + (wn * 32 + l7) * 128;

    for (int i = tid; i < 768; i += 256) {
        int buf = i >= 384;
        As[buf * 6656 + 6272 + (i & 383)] = 0u;
    }

    auto issue = [&](int kc, int buf) {
        for (int idx = tid; idx < 1568; idx += 256) {
            int row = idx >> 3;
            int q = idx & 7;
            uint32_t dst = as_b + (buf * 6656 + row * 32 + ((q ^ (row & 7)) << 2)) * 4;
            cp_async16(dst, A + (size_t)row * DIM + kc * 64 + q * 8);
        }
        for (int idx = tid; idx < 1024; idx += 256) {
            int r = idx >> 3;
            int q = idx & 7;
            uint32_t dst = ws_b + (buf * 4096 + r * 32 + ((q ^ (r & 7)) << 2)) * 4;
            cp_async16(dst, Wp + (size_t)r * DIM + kc * 64 + q * 8);
        }
        cp_commit();
    };

    float acc[4][4][4];
    #pragma unroll
    for (int mt = 0; mt < 4; mt++)
        #pragma unroll
        for (int nf = 0; nf < 4; nf++)
            #pragma unroll
            for (int c = 0; c < 4; c++) acc[mt][nf][c] = 0.0f;

    issue(0, 0);
    for (int kc = 0; kc < 12; kc++) {
        int buf = kc & 1;
        if (kc < 11) { issue(kc + 1, buf ^ 1); cp_wait<1>(); }
        else cp_wait<0>();
        __syncthreads();
        uint32_t aBuf = aLaneBase + buf * 26624;
        uint32_t bBuf = bLaneBase + buf * 16384;

        #pragma unroll
        for (int ks = 0; ks < 4; ks++) {
            int gB = 2 * ks + halfB;
            uint32_t bOff = (uint32_t)((gB ^ l7) << 4);
            uint32_t bh0[4], bh1[4], bl0[4], bl1[4];
            #pragma unroll
            for (int nf = 0; nf < 4; nf++) {
                ldsm_x2(bh0[nf], bh1[nf], bBuf + nf * 1024 + bOff);
                ldsm_x2(bl0[nf], bl1[nf], bBuf + 8192 + nf * 1024 + bOff);
            }
            int gA = 2 * ks + halfA;
            uint32_t aOff = (uint32_t)((gA ^ swA) << 4);
            #pragma unroll
            for (int mt = 0; mt < 4; mt++) {
                int mtg = wm + 4 * mt;
                if (mtg < 13) {
                    uint32_t a0, a1, a2, a3;
                    ldsm_x4(a0, a1, a2, a3, aBuf + mtg * 2048 + aOff);
                    #pragma unroll
                    for (int nf = 0; nf < 4; nf++) {
                        mma_bf16(acc[mt][nf], a0, a1, a2, a3, bh0[nf], bh1[nf]);
                        mma_bf16(acc[mt][nf], a0, a1, a2, a3, bl0[nf], bl1[nf]);
                    }
                }
            }
        }
        __syncthreads();
    }

    float* outp = (which ? g_proj_q : g_proj_s) + (size_t)mi * NSEQ * PP;
    #pragma unroll
    for (int nf = 0; nf < 4; nf++) {
        int cb = wn * 32 + nf * 8 + 2 * tig;
        #pragma unroll
        for (int mt = 0; mt < 4; mt++) {
            int mtg = wm + 4 * mt;
            if (mtg < 13) {
                int r0 = mtg * 16 + gid;
                int r1 = r0 + 8;
                if (r0 < NSEQ) {
                    outp[(size_t)r0 * PP + cb] = acc[mt][nf][0];
                    outp[(size_t)r0 * PP + cb + 1] = acc[mt][nf][1];
                }
                if (r1 < NSEQ) {
                    outp[(size_t)r1 * PP + cb] = acc[mt][nf][2];
                    outp[(size_t)r1 * PP + cb + 1] = acc[mt][nf][3];
                }
            }
        }
    }
}

// ---------------- 2b) BLS GEMM: n=128 tile, 512 threads, cp.async + ldmatrix ----------------
// grid = (6 n-tiles, M matrices). 16 warps: wm=warp&3 (M), wn=warp>>2 (N, 32 cols each).
#define BLS_SMEM_WORDS (2 * 6656 + 2 * 4096 + 512)
#define BLS_SMEM_BYTES (BLS_SMEM_WORDS * 4)

__global__ void __launch_bounds__(512, 1)
bls_bf16_kernel(const __nv_bfloat16* __restrict__ Abf,
                const __nv_bfloat16* __restrict__ Wt,
                const float* __restrict__ bias, int which) {
    extern __shared__ uint32_t sh[];
    uint32_t* As = sh;                 // 2 x [208 x 32]
    uint32_t* Ws = sh + 13312;         // 2 x [128 x 32]
    float (*colsum)[128] = (float(*)[128])(sh + 13312 + 8192);
    uint32_t as_b = smem_to_u32(As);
    uint32_t ws_b = smem_to_u32(Ws);

    int nt = blockIdx.x;
    int mi = blockIdx.y;
    int n0 = nt * 128;
    const __nv_bfloat16* A = Abf + (size_t)mi * NSEQ * DIM;

    int tid = threadIdx.x;
    int lane = tid & 31;
    int warp = tid >> 5;
    int wm = warp & 3;                 // M split (4)
    int wn = warp >> 2;                // N split (4) x 32 cols
    int gid = lane >> 2;
    int tig = lane & 3;

    int l15 = lane & 15;
    int halfA = lane >> 4;
    int swA = lane & 7;
    int l7 = lane & 7;
    int halfB = (lane >> 3) & 1;
    uint32_t aLaneBase = as_b + l15 * 128;
    uint32_t bLaneBase = ws_b + (wn * 32 + l7) * 128;

    for (int i = tid; i < 768; i += 512) {
        int buf = i >= 384;
        As[buf * 6656 + 6272 + (i & 383)] = 0u;
    }

    auto issue = [&](int kc, int buf) {
        for (int idx = tid; idx < 1568; idx += 512) {
            int row = idx >> 3;
            int q = idx & 7;
            uint32_t dst = as_b + (buf * 6656 + row * 32 + ((q ^ (row & 7)) << 2)) * 4;
            cp_async16(dst, A + (size_t)row * DIM + kc * 64 + q * 8);
        }
        for (int idx = tid; idx < 1024; idx += 512) {
            int r = idx >> 3;              // 0..127
            int q = idx & 7;
            uint32_t dst = ws_b + (buf * 4096 + r * 32 + ((q ^ (r & 7)) << 2)) * 4;
            cp_async16(dst, Wt + (size_t)(n0 + r) * DIM + kc * 64 + q * 8);
        }
        cp_commit();
    };

    float acc[4][4][4];
    #pragma unroll
    for (int mt = 0; mt < 4; mt++)
        #pragma unroll
        for (int nf = 0; nf < 4; nf++)
            #pragma unroll
            for (int c = 0; c < 4; c++) acc[mt][nf][c] = 0.0f;

    issue(0, 0);
    for (int kc = 0; kc < 12; kc++) {
        int buf = kc & 1;
        if (kc < 11) { issue(kc + 1, buf ^ 1); cp_wait<1>(); }
        else cp_wait<0>();
        __syncthreads();
        uint32_t aBuf = aLaneBase + buf * 26624;
        uint32_t bBuf = bLaneBase + buf * 16384;

        #pragma unroll
        for (int ks = 0; ks < 4; ks++) {
            int gB = 2 * ks + halfB;
            uint32_t bOff = (uint32_t)((gB ^ l7) << 4);
            uint32_t b0[4], b1[4];
            #pragma unroll
            for (int nf = 0; nf < 4; nf++)
                ldsm_x2(b0[nf], b1[nf], bBuf + nf * 1024 + bOff);
            int gA = 2 * ks + halfA;
            uint32_t aOff = (uint32_t)((gA ^ swA) << 4);
            #pragma unroll
            for (int mt = 0; mt < 4; mt++) {
                int mtg = wm + 4 * mt;
                if (mtg < 13) {
                    uint32_t a0, a1, a2, a3;
                    ldsm_x4(a0, a1, a2, a3, aBuf + mtg * 2048 + aOff);
                    #pragma unroll
                    for (int nf = 0; nf < 4; nf++)
                        mma_bf16(acc[mt][nf], a0, a1, a2, a3, b0[nf], b1[nf]);
                }
            }
        }
        __syncthreads();
    }

    // epilogue: tanh(acc + bias) column-mean over valid rows
    #pragma unroll
    for (int nf = 0; nf < 4; nf++) {
        int cb = n0 + wn * 32 + nf * 8 + 2 * tig;
        float bv0 = bias[cb];
        float bv1 = bias[cb + 1];
        float p0 = 0.0f, p1 = 0.0f;
        #pragma unroll
        for (int mt = 0; mt < 4; mt++) {
            int mtg = wm + 4 * mt;
            if (mtg < 13) {
                int r0 = mtg * 16 + gid;
                int r1 = r0 + 8;
                if (r0 < NSEQ) {
                    p0 += tanhf(acc[mt][nf][0] + bv0);
                    p1 += tanhf(acc[mt][nf][1] + bv1);
                }
                if (r1 < NSEQ) {
                    p0 += tanhf(acc[mt][nf][2] + bv0);
                    p1 += tanhf(acc[mt][nf][3] + bv1);
                }
            }
        }
        #pragma unroll
        for (int off = 4; off <= 16; off <<= 1) {
            p0 += __shfl_xor_sync(0xffffffff, p0, off);
            p1 += __shfl_xor_sync(0xffffffff, p1, off);
        }
        if (gid == 0) {
            colsum[wm][wn * 32 + nf * 8 + 2 * tig]     = p0;
            colsum[wm][wn * 32 + nf * 8 + 2 * tig + 1] = p1;
        }
    }
    __syncthreads();
    if (tid < 128) {
        float s = colsum[0][tid] + colsum[1][tid] + colsum[2][tid] + colsum[3][tid];
        float* outp = which ? g_bls_q : g_bls_s;
        outp[(size_t)mi * DIM + n0 + tid] = s * (1.0f / NSEQ);
    }
}

// ---------------- 3) cov + Newton-Schulz matrix sqrt ----------------
#define CS_SMEM_FLOATS (NSEQ * 65 + 3 * 64 * 65 + 256 + 64)

__global__ void covsqrt_kernel(int which) {
    extern __shared__ float fsh[];
    float* X = fsh;
    float* Yb = X + NSEQ * 65;
    float* Zb = Yb + 64 * 65;
    float* Tb = Zb + 64 * 65;
    float* red = Tb + 64 * 65;
    float* mean = red + 256;

    const float* proj = which ? g_proj_q : g_proj_s;
    float* cs = which ? g_cs_q : g_cs_s;
    int mi = blockIdx.x;
    int tx = threadIdx.x, ty = threadIdx.y;
    int tid = ty * 16 + tx;

    for (int idx = tid; idx < NSEQ * PP; idx += 256) {
        int n = idx >> 6;
        int p = idx & 63;
        X[n * 65 + p] = proj[(size_t)mi * NSEQ * PP + idx];
    }
    __syncthreads();
    if (tid < 64) {
        float s = 0.0f;
        for (int n = 0; n < NSEQ; n++) s += X[n * 65 + tid];
        mean[tid] = s * (1.0f / NSEQ);
    }
    __syncthreads();
    for (int idx = tid; idx < NSEQ * PP; idx += 256) {
        int n = idx >> 6;
        int p = idx & 63;
        X[n * 65 + p] -= mean[p];
    }
    __syncthreads();

    float cacc[4][4];
    #pragma unroll
    for (int i = 0; i < 4; i++)
        #pragma unroll
        for (int j = 0; j < 4; j++) cacc[i][j] = 0.0f;
    for (int n = 0; n < NSEQ; n++) {
        float a[4], b[4];
        #pragma unroll
        for (int i = 0; i < 4; i++) a[i] = X[n * 65 + ty + 16 * i];
        #pragma unroll
        for (int j = 0; j < 4; j++) b[j] = X[n * 65 + tx + 16 * j];
        #pragma unroll
        for (int i = 0; i < 4; i++)
            #pragma unroll
            for (int j = 0; j < 4; j++) cacc[i][j] += a[i] * b[j];
    }
    float ss = 0.0f;
    #pragma unroll
    for (int i = 0; i < 4; i++) {
        int p = ty + 16 * i;
        #pragma unroll
        for (int j = 0; j < 4; j++) {
            int q = tx + 16 * j;
            float v = cacc[i][j] * (1.0f / 195.0f) + ((p == q) ? 1e-5f : 0.0f);
            Yb[p * 65 + q] = v;
            ss += v * v;
        }
    }
    float total = block_reduce_sum(ss, red, tid);
    float norm = sqrtf(total);
    float inv = 1.0f / (norm + 1e-8f);
    #pragma unroll
    for (int i = 0; i < 4; i++) {
        int p = ty + 16 * i;
        #pragma unroll
        for (int j = 0; j < 4; j++) {
            int q = tx + 16 * j;
            Yb[p * 65 + q] *= inv;
        }
    }
    __syncthreads();

    // ---- iteration 0 (Z = I): T = 1.5I - 0.5*Y ; Ynew = Y@T ; Znew = T ----
    {
        #pragma unroll
        for (int i = 0; i < 4; i++) {
            int p = ty + 16 * i;
            #pragma unroll
            for (int j = 0; j < 4; j++) {
                int q = tx + 16 * j;
                Tb[p * 65 + q] = ((p == q) ? 1.5f : 0.0f) - 0.5f * Yb[p * 65 + q];
            }
        }
        __syncthreads();
        float yacc[4][4];
        #pragma unroll
        for (int i = 0; i < 4; i++)
            #pragma unroll
            for (int j = 0; j < 4; j++) yacc[i][j] = 0.0f;
        for (int k = 0; k < 64; k++) {
            float ya[4], tb[4];
            #pragma unroll
            for (int i = 0; i < 4; i++) ya[i] = Yb[(ty + 16 * i) * 65 + k];
            #pragma unroll
            for (int j = 0; j < 4; j++) tb[j] = Tb[k * 65 + tx + 16 * j];
            #pragma unroll
            for (int i = 0; i < 4; i++)
                #pragma unroll
                for (int j = 0; j < 4; j++) yacc[i][j] += ya[i] * tb[j];
        }
        __syncthreads();
        #pragma unroll
        for (int i = 0; i < 4; i++) {
            int p = ty + 16 * i;
            #pragma unroll
            for (int j = 0; j < 4; j++) {
                int q = tx + 16 * j;
                Yb[p * 65 + q] = yacc[i][j];
                Zb[p * 65 + q] = Tb[p * 65 + q];
            }
        }
        __syncthreads();
    }

    // ---- iterations 1..2 (full) ----
    for (int it = 1; it < 3; it++) {
        float tacc[4][4];
        #pragma unroll
        for (int i = 0; i < 4; i++)
            #pragma unroll
            for (int j = 0; j < 4; j++) tacc[i][j] = 0.0f;
        for (int k = 0; k < 64; k++) {
            float a[4], b[4];
            #pragma unroll
            for (int i = 0; i < 4; i++) a[i] = Zb[(ty + 16 * i) * 65 + k];
            #pragma unroll
            for (int j = 0; j < 4; j++) b[j] = Yb[k * 65 + tx + 16 * j];
            #pragma unroll
            for (int i = 0; i < 4; i++)
                #pragma unroll
                for (int j = 0; j < 4; j++) tacc[i][j] += a[i] * b[j];
        }
        #pragma unroll
        for (int i = 0; i < 4; i++) {
            int p = ty + 16 * i;
            #pragma unroll
            for (int j = 0; j < 4; j++) {
                int q = tx + 16 * j;
                Tb[p * 65 + q] = ((p == q) ? 1.5f : 0.0f) - 0.5f * tacc[i][j];
            }
        }
        __syncthreads();
        float yacc[4][4], zacc[4][4];
        #pragma unroll
        for (int i = 0; i < 4; i++)
            #pragma unroll
            for (int j = 0; j < 4; j++) { yacc[i][j] = 0.0f; zacc[i][j] = 0.0f; }
        for (int k = 0; k < 64; k++) {
            float ya[4], tb[4], ta[4], zb2[4];
            #pragma unroll
            for (int i = 0; i < 4; i++) {
                ya[i] = Yb[(ty + 16 * i) * 65 + k];
                ta[i] = Tb[(ty + 16 * i) * 65 + k];
            }
            #pragma unroll
            for (int j = 0; j < 4; j++) {
                tb[j] = Tb[k * 65 + tx + 16 * j];
                zb2[j] = Zb[k * 65 + tx + 16 * j];
            }
            #pragma unroll
            for (int i = 0; i < 4; i++)
                #pragma unroll
                for (int j = 0; j < 4; j++) {
                    yacc[i][j] += ya[i] * tb[j];
                    zacc[i][j] += ta[i] * zb2[j];
                }
        }
        __syncthreads();
        #pragma unroll
        for (int i = 0; i < 4; i++) {
            int p = ty + 16 * i;
            #pragma unroll
            for (int j = 0; j < 4; j++) {
                int q = tx + 16 * j;
                Yb[p * 65 + q] = yacc[i][j];
                Zb[p * 65 + q] = zacc[i][j];
            }
        }
        __syncthreads();
    }

    float sc = sqrtf(norm + 1e-8f);
    #pragma unroll
    for (int i = 0; i < 4; i++) {
        int p = ty + 16 * i;
        #pragma unroll
        for (int j = 0; j < 4; j++) {
            int q = tx + 16 * j;
            cs[(size_t)mi * 4096 + p * 64 + q] = Yb[p * 65 + q] * sc;
        }
    }
}

// ---------------- 4) fuse (both sets in one launch) ----------------
__global__ void fuse_kernel() {
    int gb = blockIdx.x;
    int which = gb >= GS;
    int g = which ? gb - GS : gb;
    const float* gap = which ? g_gap_q : g_gap_s;
    const float* cs = which ? g_cs_q : g_cs_s;
    const float* bls = which ? g_bls_q : g_bls_s;
    float* z = which ? g_z_q : g_z_s;
    int Mt = which ? MTQ : MTS;

    __shared__ float buf[DF];
    __shared__ float red[256];
    int tid = threadIdx.x;
    int m0 = g * NV;

    float ss0 = 0.0f, ss1 = 0.0f, ss2 = 0.0f;

    for (int j = tid; j < SEC0; j += 256) {
        int l = j / DIM;
        int f = j - l * DIM;
        const float* src = gap + ((size_t)(l * Mt + m0)) * DIM + f;
        float v = 0.0f;
        #pragma unroll
        for (int vi = 0; vi < NV; vi++) v += src[(size_t)vi * DIM];
        v *= (1.0f / NV);
        float t = tukey_f(v);
        buf[j] = t;
        ss0 += t * t;
    }
    for (int j = tid; j < SEC1; j += 256) {
        int l = j / TRI;
        int f = j - l * TRI;
        int i = 0, rem = f;
        while (rem >= 64 - i) { rem -= 64 - i; i++; }
        int jj = i + rem;
        const float* src = cs + ((size_t)(l * Mt + m0)) * 4096 + i * 64 + jj;
        float v = 0.0f;
        #pragma unroll
        for (int vi = 0; vi < NV; vi++) v += src[(size_t)vi * 4096];
        v *= (1.0f / NV);
        float t = tukey_f(v);
        buf[SEC0 + j] = t;
        ss1 += t * t;
    }
    for (int j = tid; j < SEC0; j += 256) {
        int l = j / DIM;
        int f = j - l * DIM;
        const float* src = bls + ((size_t)(l * Mt + m0)) * DIM + f;
        float v = 0.0f;
        #pragma unroll
        for (int vi = 0; vi < NV; vi++) v += src[(size_t)vi * DIM];
        v *= (1.0f / NV);
        float t = tukey_f(v);
        buf[SEC0 + SEC1 + j] = t;
        ss2 += t * t;
    }
    __syncthreads();
    float S0 = block_reduce_sum(ss0, red, tid);
    float S1 = block_reduce_sum(ss1, red, tid);
    float S2 = block_reduce_sum(ss2, red, tid);
    float inv0 = 1.0f / fmaxf(sqrtf(S0), 1e-12f) * 1.0f;
    float inv1 = 1.0f / fmaxf(sqrtf(S1), 1e-12f) * 0.8f;
    float inv2 = 1.0f / fmaxf(sqrtf(S2), 1e-12f) * 0.1f;

    for (int j = tid; j < DF; j += 256) {
        float w = (j < SEC0) ? inv0 : (j < SEC0 + SEC1) ? inv1 : inv2;
        z[(size_t)g * DF + j] = buf[j] * w;
    }
}

// ---------------- 5) per-(b,feature) stats ----------------
__global__ void stats_kernel() {
    int idx = blockIdx.x * 256 + threadIdx.x;
    if (idx >= BB * DF) return;
    int b = idx / DF;
    int f = idx - b * DF;
    {
        const float* zs = g_z_s + (size_t)b * NSUP * DF + f;
        float m = 0.0f;
        for (int s = 0; s < NSUP; s++) m += zs[(size_t)s * DF];
        m *= (1.0f / NSUP);
        float v = 0.0f;
        for (int s = 0; s < NSUP; s++) { float d = zs[(size_t)s * DF] - m; v += d * d; }
        v *= (1.0f / (NSUP - 1));
        g_mu_s[idx] = m;
        g_std_s[idx] = sqrtf(v) + 1e-8f;
    }
    {
        const float* zq = g_z_q + (size_t)b * NQRY * DF + f;
        float m = 0.0f;
        for (int s = 0; s < NQRY; s++) m += zq[(size_t)s * DF];
        m *= (1.0f / NQRY);
        float v = 0.0f;
        for (int s = 0; s < NQRY; s++) { float d = zq[(size_t)s * DF] - m; v += d * d; }
        v *= (1.0f / (NQRY - 1));
        g_mu_q[idx] = m;
        g_std_q[idx] = sqrtf(v) + 1e-8f;
    }
}

// ---------------- 6) center/standardize + row l2norm (both sets) ----------------
__global__ void rownorm_kernel() {
    __shared__ float red[256];
    int gb = blockIdx.x;
    int tid = threadIdx.x;
    if (gb < GS) {
        int g = gb;
        int b = g / NSUP;
        float* z = g_z_s + (size_t)g * DF;
        const float* mu = g_mu_s + (size_t)b * DF;
        float ss = 0.0f;
        for (int f = tid; f < DF; f += 256) { float v = z[f] - mu[f]; ss += v * v; }
        float S = block_reduce_sum(ss, red, tid);
        float inv = 1.0f / fmaxf(sqrtf(S), 1e-12f);
        for (int f = tid; f < DF; f += 256) z[f] = (z[f] - mu[f]) * inv;
    } else {
        int g = gb - GS;
        int b = g / NQRY;
        float* z = g_z_q + (size_t)g * DF;
        const float* muq = g_mu_q + (size_t)b * DF;
        const float* sdq = g_std_q + (size_t)b * DF;
        const float* sds = g_std_s + (size_t)b * DF;
        float ss = 0.0f;
        for (int f = tid; f < DF; f += 256) {
            float v = (z[f] - muq[f]) / sdq[f] * sds[f];
            ss += v * v;
        }
        float S = block_reduce_sum(ss, red, tid);
        float inv = 1.0f / fmaxf(sqrtf(S), 1e-12f);
        for (int f = tid; f < DF; f += 256) {
            float v = (z[f] - muq[f]) / sdq[f] * sds[f];
            z[f] = v * inv;
        }
    }
}

// ---------------- 7) gram ----------------
__global__ void gram_kernel() {
    int b = blockIdx.x;
    int i = blockIdx.y;
    int tid = threadIdx.x;
    const float* rowi = (i < NSUP)
        ? g_z_s + (size_t)(b * NSUP + i) * DF
        : g_z_q + (size_t)(b * NQRY + (i - NSUP)) * DF;
    const float* zsb = g_z_s + (size_t)b * NSUP * DF;

    float part[NSUP];
    #pragma unroll
    for (int j = 0; j < NSUP; j++) part[j] = 0.0f;
    for (int f = tid; f < DF; f += 256) {
        float a = rowi[f];
        #pragma unroll
        for (int j = 0; j < NSUP; j++) part[j] += a * zsb[(size_t)j * DF + f];
    }
    __shared__ float red[256];
    for (int j = 0; j < NSUP; j++) {
        red[tid] = part[j];
        __syncthreads();
        for (int s = 128; s > 0; s >>= 1) {
            if (tid < s) red[tid] += red[tid + s];
            __syncthreads();
        }
        if (tid == 0) g_gram[(b * 75 + i) * 25 + j] = red[0];
        __syncthreads();
    }
}

// ---------------- 8) ridge solve + output ----------------
__global__ void solve_kernel(const int* __restrict__ y_sup, float* __restrict__ out) {
    int b = blockIdx.x;
    int tid = threadIdx.x;
    __shared__ float Ab[25][31];
    __shared__ float alpha[25][5];
    const float lam = 0.1f * ((float)DF / 500.0f);

    for (int idx = tid; idx < 25 * 30; idx += 32) {
        int i = idx / 30;
        int j = idx - i * 30;
        if (j < 25) {
            Ab[i][j] = g_gram[(b * 75 + i) * 25 + j] + ((i == j) ? lam : 0.0f);
        } else {
            int c = j - 25;
            Ab[i][j] = (y_sup[b * NSUP + i] == c) ? 1.0f : 0.0f;
        }
    }
    __syncthreads();
    for (int k = 0; k < 25; k++) {
        if (tid < 25 && tid != k) {
            float factor = Ab[tid][k] / Ab[k][k];
            for (int j = k; j < 30; j++) Ab[tid][j] -= factor * Ab[k][j];
        }
        __syncthreads();
    }
    for (int idx = tid; idx < 125; idx += 32) {
        int i = idx / 5;
        int c = idx - i * 5;
        alpha[i][c] = Ab[i][25 + c] / Ab[i][i];
    }
    __syncthreads();
    for (int idx = tid; idx < NQRY * NC; idx += 32) {
        int q = idx / NC;
        int c = idx - q * NC;
        float s = 0.0f;
        #pragma unroll
        for (int j = 0; j < 25; j++) s += g_gram[(b * 75 + 25 + q) * 25 + j] * alpha[j][c];
        out[((size_t)b * NQRY + q) * NC + c] = 20.0f * s;
    }
}

// ---------------- launch ----------------
extern "C" void kernel_launch(void* const* d_in, const int* in_sizes, int n_in,
                              void* d_out, int out_size) {
    const float* feats_sup   = (const float*)d_in[0];
    const float* feats_qry   = (const float*)d_in[1];
    const float* cov_reducer = (const float*)d_in[2];
    const float* w_bls       = (const float*)d_in[3];
    const float* b_bls       = (const float*)d_in[4];
    const int*   y_sup       = (const int*)d_in[5];
    float* out = (float*)d_out;

    static const size_t CS_SMEM = (size_t)CS_SMEM_FLOATS * sizeof(float);
    cudaFuncSetAttribute(covsqrt_kernel, cudaFuncAttributeMaxDynamicSharedMemorySize, (int)CS_SMEM);
    cudaFuncSetAttribute(bls_bf16_kernel, cudaFuncAttributeMaxDynamicSharedMemorySize, BLS_SMEM_BYTES);
    cudaFuncSetAttribute(proj_bf16_kernel, cudaFuncAttributeMaxDynamicSharedMemorySize, PROJ_SMEM_BYTES);

    dim3 blk2d(16, 16);

    __nv_bfloat16 *ab_s, *ab_q, *wtb, *wp;
    cudaGetSymbolAddress((void**)&ab_s, g_ab_s);
    cudaGetSymbolAddress((void**)&ab_q, g_ab_q);
    cudaGetSymbolAddress((void**)&wtb, g_wtb);
    cudaGetSymbolAddress((void**)&wp, g_wp);

    // fused streaming bf16 convert + gap (both sets, one launch)
    convert_gap_kernel<<<MS + MQ, 192>>>(feats_sup, feats_qry, ab_s, ab_q);
    convert_wt_kernel<<<dim3(24, 24), dim3(32, 8)>>>(w_bls);
    convert_wp_kernel<<<dim3(2, 24), dim3(32, 8)>>>(cov_reducer);

    // projection GEMM (bf16 tensor cores, W hi/lo split, ldmatrix)
    proj_bf16_kernel<<<MS, 256, PROJ_SMEM_BYTES>>>(ab_s, wp, 0);
    proj_bf16_kernel<<<MQ, 256, PROJ_SMEM_BYTES>>>(ab_q, wp, 1);

    // BLS GEMM (bf16 tensor cores, n=128 tiles, cp.async + ldmatrix)
    bls_bf16_kernel<<<dim3(6, MS), 512, BLS_SMEM_BYTES>>>(ab_s, wtb, b_bls, 0);
    bls_bf16_kernel<<<dim3(6, MQ), 512, BLS_SMEM_BYTES>>>(ab_q, wtb, b_bls, 1);

    // cov + Newton-Schulz sqrt
    covsqrt_kernel<<<MS, blk2d, CS_SMEM>>>(0);
    covsqrt_kernel<<<MQ, blk2d, CS_SMEM>>>(1);

    // fuse (both sets)
    fuse_kernel<<<GS + GQ, 256>>>();

    // stats
    stats_kernel<<<(BB * DF + 255) / 256, 256>>>();

    // center + l2norm rows (both sets)
    rownorm_kernel<<<GS + GQ, 256>>>();

    // gram
    gram_kernel<<<dim3(BB, 75), 256>>>();

    // solve + logits
    solve_kernel<<<BB, 32>>>(y_sup, out);
}